// round 9
// baseline (speedup 1.0000x reference)
#include <cuda_runtime.h>
#include <cuda_fp16.h>
#include <cstdint>

#define N_NODES 20000
#define N_EDGES 320000
#define ET      (N_EDGES + N_NODES)   // 340000
#define GCN_IN  256
#define C1      128
#define H1      5
#define F1      (H1*C1)               // 640
#define C2      128
#define H2      3
#define F2      (H2*C2)               // 384
#define N_BBOX  4096
#define NB_SCAN ((N_NODES + 1023) / 1024)   // 20

// ---------------- scratch ---------------------------------------------------
__device__ int    g_is64;
__device__ int    g_cnt[N_NODES];
__device__ int    g_cur[N_NODES];
__device__ int    g_off[N_NODES + 1];
__device__ int    g_src[ET];
__device__ int    g_dst[ET];
__device__ int    g_bsum[32];
__device__ int    g_bpre[32];
__device__ float  g_xr[(size_t)N_NODES * GCN_IN];   // tf32-rounded x
__device__ float  g_w1t[F1 * GCN_IN];               // W1^T tf32 [F1][256]
__device__ float  g_w2t[F2 * F1];                   // W2^T tf32 [F2][640]
__device__ __half g_h1h[(size_t)N_NODES * F1];      // h1 fp16 mirror (gather-only)
__device__ float  g_o1[(size_t)N_NODES * F1];       // layer1 out, tf32-rounded
__device__ float  g_h2[(size_t)N_NODES * F2];
__device__ float  g_as1[N_NODES * H1];
__device__ float  g_ad1[N_NODES * H1];
__device__ float  g_as2[N_NODES * H2];
__device__ float  g_ad2[N_NODES * H2];
__device__ float  g_dsum1[N_NODES * H1];
__device__ float  g_dsum2[N_NODES * H2];
__device__ float  g_alpha1[(size_t)ET * H1];
__device__ float  g_alpha2[(size_t)ET * H2];

__device__ __forceinline__ float leaky(float x, float s) {
    return x >= 0.f ? x : s * x;
}
__device__ __forceinline__ int load_idx(const void* p, long long i) {
    return g_is64 ? (int)((const long long*)p)[i] : ((const int*)p)[i];
}
__device__ __forceinline__ uint32_t f2tf32(float x) {
    uint32_t u;
    asm("cvt.rna.tf32.f32 %0, %1;" : "=r"(u) : "f"(x));
    return u;
}
__device__ __forceinline__ void ldm_x4(uint32_t (&r)[4], uint32_t addr) {
    asm volatile("ldmatrix.sync.aligned.m8n8.x4.shared.b16 {%0,%1,%2,%3}, [%4];"
                 : "=r"(r[0]), "=r"(r[1]), "=r"(r[2]), "=r"(r[3]) : "r"(addr));
}

// ---------------- dtype sniff -----------------------------------------------
__global__ void k_detect(const void* ei) {
    const int* p = (const int*)ei;
    int nz = 0;
    #pragma unroll
    for (int i = 0; i < 64; i++) nz |= p[2 * i + 1];
    g_is64 = (nz == 0) ? 1 : 0;
}

// ---------------- tf32 pre-round (float4) -----------------------------------
__global__ void k_round(const float* __restrict__ in, float* __restrict__ out, int n4) {
    int i = blockIdx.x * blockDim.x + threadIdx.x;
    if (i >= n4) return;
    float4 v = reinterpret_cast<const float4*>(in)[i];
    v.x = __uint_as_float(f2tf32(v.x));
    v.y = __uint_as_float(f2tf32(v.y));
    v.z = __uint_as_float(f2tf32(v.z));
    v.w = __uint_as_float(f2tf32(v.w));
    reinterpret_cast<float4*>(out)[i] = v;
}

// ---------------- transpose + round: W[K][N] -> Wt[N][K] --------------------
__global__ void k_transpose(const float* __restrict__ in, float* __restrict__ out,
                            int K, int N) {
    __shared__ float tile[32][33];
    int n0 = blockIdx.x * 32, k0 = blockIdx.y * 32;
    int tx = threadIdx.x, ty = threadIdx.y;
    #pragma unroll
    for (int j = 0; j < 32; j += 8)
        tile[ty + j][tx] = in[(size_t)(k0 + ty + j) * N + n0 + tx];
    __syncthreads();
    #pragma unroll
    for (int j = 0; j < 32; j += 8)
        out[(size_t)(n0 + ty + j) * K + k0 + tx] =
            __uint_as_float(f2tf32(tile[tx][ty + j]));
}

// ---------------- CSR build -------------------------------------------------
__global__ void k_zero() {
    int i = blockIdx.x * blockDim.x + threadIdx.x;
    if (i < N_NODES) { g_cnt[i] = 0; g_cur[i] = 0; }
    if (i < N_NODES * H1) g_dsum1[i] = 0.f;
    if (i < N_NODES * H2) g_dsum2[i] = 0.f;
}

__global__ void k_hist(const void* __restrict__ ei) {
    int e = blockIdx.x * blockDim.x + threadIdx.x;
    if (e >= ET) return;
    int dst = (e < N_EDGES) ? load_idx(ei, (long long)N_EDGES + e) : (e - N_EDGES);
    atomicAdd(&g_cnt[dst], 1);
}

__global__ void k_scan1() {
    __shared__ int ws[32];
    int tid = threadIdx.x, lane = tid & 31, wid = tid >> 5;
    int i = blockIdx.x * 1024 + tid;
    int v = (i < N_NODES) ? g_cnt[i] : 0;
    int x = v;
    #pragma unroll
    for (int o = 1; o < 32; o <<= 1) {
        int y = __shfl_up_sync(~0u, x, o);
        if (lane >= o) x += y;
    }
    if (lane == 31) ws[wid] = x;
    __syncthreads();
    if (wid == 0) {
        int w = ws[lane];
        #pragma unroll
        for (int o = 1; o < 32; o <<= 1) {
            int y = __shfl_up_sync(~0u, w, o);
            if (lane >= o) w += y;
        }
        ws[lane] = w;
    }
    __syncthreads();
    int incl = x + (wid > 0 ? ws[wid - 1] : 0);
    if (i < N_NODES) g_off[i + 1] = incl;
    if (tid == 1023) g_bsum[blockIdx.x] = incl;
}

__global__ void k_scan2() {
    int lane = threadIdx.x;
    int v = (lane < NB_SCAN) ? g_bsum[lane] : 0;
    int x = v;
    #pragma unroll
    for (int o = 1; o < 32; o <<= 1) {
        int y = __shfl_up_sync(~0u, x, o);
        if (lane >= o) x += y;
    }
    g_bpre[lane] = x - v;
}

__global__ void k_scan3() {
    int i = blockIdx.x * 1024 + threadIdx.x;
    if (i == 0) g_off[0] = 0;
    if (i < N_NODES) g_off[i + 1] += g_bpre[blockIdx.x];
}

__global__ void k_scatter(const void* __restrict__ ei) {
    int e = blockIdx.x * blockDim.x + threadIdx.x;
    if (e >= ET) return;
    int src, dst;
    if (e < N_EDGES) {
        src = load_idx(ei, e);
        dst = load_idx(ei, (long long)N_EDGES + e);
    } else {
        src = dst = e - N_EDGES;
    }
    int p = g_off[dst] + atomicAdd(&g_cur[dst], 1);
    g_src[p] = src;
    g_dst[p] = dst;
}

// ---------------- TF32 GEMM: ldmatrix + fused attention dots ----------------
// MODE 0 stores C as fp16 mirror (gather-only consumer); MODE 1 stores fp32.
#define GBM 128
#define GBN 128
#define GBK 16
#define SA  20
#define SBK 20
#define STG 3
#define GEMM_SMEM (STG * (GBM * SA + GBN * SBK) * 4)

template<int MODE>
__global__ void __launch_bounds__(256, 2)
gemm_tf32(const float* __restrict__ asrc, const float* __restrict__ adst) {
    const int M = N_NODES;
    const int K = (MODE == 0) ? GCN_IN : F1;
    const int N = (MODE == 0) ? F1 : F2;
    const int H = (MODE == 0) ? H1 : H2;
    const float* A  = (MODE == 0) ? (const float*)g_xr  : (const float*)g_o1;
    const float* Bt = (MODE == 0) ? (const float*)g_w1t : (const float*)g_w2t;
    float* oas = (MODE == 0) ? g_as1 : g_as2;
    float* oad = (MODE == 0) ? g_ad1 : g_ad2;

    extern __shared__ float smem[];
    float* As = smem;                        // [STG][GBM*SA]
    float* Bs = smem + STG * GBM * SA;       // [STG][GBN*SBK]
    __shared__ float red_s[GBM], red_d[GBM];

    int tid = threadIdx.x, lane = tid & 31, warp = tid >> 5;
    int warp_m = (warp & 3) * 32;
    int warp_n = (warp >> 2) * 64;
    int head = blockIdx.x;
    int rb = blockIdx.y * GBM, cb = head * GBN;
    int grp = lane >> 2, sub = lane & 3;

    const int arow = tid >> 2;
    const int acol = (tid & 3) * 4;
    const int brow = tid >> 2;
    const int bcol = (tid & 3) * 4;

    uint32_t sAb = (uint32_t)__cvta_generic_to_shared(As);
    uint32_t sBb = (uint32_t)__cvta_generic_to_shared(Bs);
    uint32_t aoff = sAb + (((lane & 15) + warp_m) * SA + ((lane >> 4) << 2)) * 4;
    uint32_t boff = sBb + (((lane & 15) + warp_n) * SBK + ((lane >> 4) << 2)) * 4;

    float acc[2][8][4];
    #pragma unroll
    for (int i = 0; i < 2; i++)
        #pragma unroll
        for (int j = 0; j < 8; j++)
            #pragma unroll
            for (int q = 0; q < 4; q++) acc[i][j][q] = 0.f;

    auto copy_tile = [&](int t, int buf) {
        int k0 = t * GBK;
        float* Ab = As + buf * GBM * SA;
        float* Bb = Bs + buf * GBN * SBK;
        #pragma unroll
        for (int p = 0; p < 2; p++) {
            int r = p * 64 + arow;
            const float* src = A + (size_t)(rb + r) * K + k0 + acol;
            uint32_t dst = (uint32_t)__cvta_generic_to_shared(&Ab[r * SA + acol]);
            int sz = (rb + r < M) ? 16 : 0;
            asm volatile("cp.async.cg.shared.global [%0], [%1], 16, %2;\n"
                         :: "r"(dst), "l"(src), "r"(sz));
        }
        #pragma unroll
        for (int p = 0; p < 2; p++) {
            int r = p * 64 + brow;
            const float* src = Bt + (size_t)(cb + r) * K + k0 + bcol;
            uint32_t dst = (uint32_t)__cvta_generic_to_shared(&Bb[r * SBK + bcol]);
            asm volatile("cp.async.cg.shared.global [%0], [%1], 16;\n"
                         :: "r"(dst), "l"(src));
        }
        asm volatile("cp.async.commit_group;\n" ::: "memory");
    };

    const int T = K / GBK;
    copy_tile(0, 0);
    copy_tile(1, 1);

    for (int t = 0; t < T; t++) {
        if (t < T - 1)
            asm volatile("cp.async.wait_group 1;\n" ::: "memory");
        else
            asm volatile("cp.async.wait_group 0;\n" ::: "memory");
        __syncthreads();
        if (t + 2 < T) copy_tile(t + 2, (t + 2) % STG);

        int buf = t % STG;
        uint32_t aB = aoff + buf * (GBM * SA * 4);
        uint32_t bB = boff + buf * (GBN * SBK * 4);

        #pragma unroll
        for (int kk = 0; kk < 2; kk++) {
            uint32_t a0[4], a1[4];
            ldm_x4(a0, aB + kk * 32);
            ldm_x4(a1, aB + kk * 32 + 16 * SA * 4);
            #pragma unroll
            for (int nt2 = 0; nt2 < 4; nt2++) {
                uint32_t b[4];
                ldm_x4(b, bB + kk * 32 + nt2 * (16 * SBK * 4));
                #pragma unroll
                for (int mt = 0; mt < 2; mt++) {
                    const uint32_t* a = (mt == 0) ? a0 : a1;
                    asm volatile(
                        "mma.sync.aligned.m16n8k8.row.col.f32.tf32.tf32.f32 "
                        "{%0,%1,%2,%3}, {%4,%5,%6,%7}, {%8,%9}, {%0,%1,%2,%3};"
                        : "+f"(acc[mt][2 * nt2][0]), "+f"(acc[mt][2 * nt2][1]),
                          "+f"(acc[mt][2 * nt2][2]), "+f"(acc[mt][2 * nt2][3])
                        : "r"(a[0]), "r"(a[1]), "r"(a[2]), "r"(a[3]),
                          "r"(b[0]), "r"(b[2]));
                    asm volatile(
                        "mma.sync.aligned.m16n8k8.row.col.f32.tf32.tf32.f32 "
                        "{%0,%1,%2,%3}, {%4,%5,%6,%7}, {%8,%9}, {%0,%1,%2,%3};"
                        : "+f"(acc[mt][2 * nt2 + 1][0]), "+f"(acc[mt][2 * nt2 + 1][1]),
                          "+f"(acc[mt][2 * nt2 + 1][2]), "+f"(acc[mt][2 * nt2 + 1][3])
                        : "r"(a[0]), "r"(a[1]), "r"(a[2]), "r"(a[3]),
                          "r"(b[1]), "r"(b[3]));
                }
            }
        }
    }

    // ---- store C (fp16 for layer 1, fp32 for layer 2) ----
    #pragma unroll
    for (int mt = 0; mt < 2; mt++) {
        int r0 = rb + warp_m + mt * 16 + grp;
        #pragma unroll
        for (int nt = 0; nt < 8; nt++) {
            int c0 = cb + warp_n + nt * 8 + 2 * sub;
            if (MODE == 0) {
                if (r0 < M)
                    *reinterpret_cast<__half2*>(g_h1h + (size_t)r0 * F1 + c0) =
                        __floats2half2_rn(acc[mt][nt][0], acc[mt][nt][1]);
                if (r0 + 8 < M)
                    *reinterpret_cast<__half2*>(g_h1h + (size_t)(r0 + 8) * F1 + c0) =
                        __floats2half2_rn(acc[mt][nt][2], acc[mt][nt][3]);
            } else {
                if (r0 < M)
                    *reinterpret_cast<float2*>(g_h2 + (size_t)r0 * F2 + c0) =
                        make_float2(acc[mt][nt][0], acc[mt][nt][1]);
                if (r0 + 8 < M)
                    *reinterpret_cast<float2*>(g_h2 + (size_t)(r0 + 8) * F2 + c0) =
                        make_float2(acc[mt][nt][2], acc[mt][nt][3]);
            }
        }
    }

    // ---- fused attention dots (fp32 accumulators) ----
    float ps[2][2] = {{0.f, 0.f}, {0.f, 0.f}};
    float pd[2][2] = {{0.f, 0.f}, {0.f, 0.f}};
    #pragma unroll
    for (int nt = 0; nt < 8; nt++) {
        int cc = warp_n + nt * 8 + 2 * sub;
        float s0 = asrc[head * 128 + cc],     d0 = adst[head * 128 + cc];
        float s1 = asrc[head * 128 + cc + 1], d1 = adst[head * 128 + cc + 1];
        #pragma unroll
        for (int mt = 0; mt < 2; mt++) {
            ps[mt][0] += acc[mt][nt][0] * s0 + acc[mt][nt][1] * s1;
            pd[mt][0] += acc[mt][nt][0] * d0 + acc[mt][nt][1] * d1;
            ps[mt][1] += acc[mt][nt][2] * s0 + acc[mt][nt][3] * s1;
            pd[mt][1] += acc[mt][nt][2] * d0 + acc[mt][nt][3] * d1;
        }
    }
    #pragma unroll
    for (int mt = 0; mt < 2; mt++)
        #pragma unroll
        for (int hf = 0; hf < 2; hf++) {
            #pragma unroll
            for (int o = 1; o < 4; o <<= 1) {
                ps[mt][hf] += __shfl_xor_sync(~0u, ps[mt][hf], o);
                pd[mt][hf] += __shfl_xor_sync(~0u, pd[mt][hf], o);
            }
        }
    if (warp >= 4 && sub == 0) {
        #pragma unroll
        for (int mt = 0; mt < 2; mt++)
            #pragma unroll
            for (int hf = 0; hf < 2; hf++) {
                int lr = warp_m + mt * 16 + hf * 8 + grp;
                red_s[lr] = ps[mt][hf];
                red_d[lr] = pd[mt][hf];
            }
    }
    __syncthreads();
    if (warp < 4 && sub == 0) {
        #pragma unroll
        for (int mt = 0; mt < 2; mt++)
            #pragma unroll
            for (int hf = 0; hf < 2; hf++) {
                int lr = warp_m + mt * 16 + hf * 8 + grp;
                int r = rb + lr;
                if (r < M) {
                    oas[r * H + head] = ps[mt][hf] + red_s[lr];
                    oad[r * H + head] = pd[mt][hf] + red_d[lr];
                }
            }
    }
}

// ---------------- edge-parallel softmax (no max-shift) ----------------------
// alpha[i][h] = exp(leaky(as[src]+ad[dst])); dsum[dst][h] += alpha
template<int H>
__global__ void k_sm_edges(const float* __restrict__ as_, const float* __restrict__ ad_,
                           float* __restrict__ alpha, float* __restrict__ dsum) {
    int i = blockIdx.x * blockDim.x + threadIdx.x;
    if (i >= ET) return;
    int s = g_src[i], d = g_dst[i];
    #pragma unroll
    for (int h = 0; h < H; h++) {
        float e = leaky(as_[s * H + h] + ad_[d * H + h], 0.2f);
        float ex = __expf(e) ;
        ex = expf(e);   // precise exp (overwrite; keep fast path dead-coded out)
        alpha[(size_t)i * H + h] = ex;
        atomicAdd(&dsum[d * H + h], ex);
    }
}

// ---------------- layer-1 aggregation: warp-per-head, fp16 gather -----------
__global__ void k_agg1(const float* __restrict__ b1) {
    int n = blockIdx.x;
    int head = threadIdx.x >> 5;           // 0..4
    int lane = threadIdx.x & 31;
    int c = head * 128 + lane * 4;
    int beg = g_off[n], end = g_off[n + 1];
    float4 acc = make_float4(0.f, 0.f, 0.f, 0.f);
    int i = beg;
    for (; i + 4 <= end; i += 4) {
        int s0 = g_src[i], s1 = g_src[i + 1], s2 = g_src[i + 2], s3 = g_src[i + 3];
        float a0 = g_alpha1[(size_t)(i    ) * H1 + head];
        float a1 = g_alpha1[(size_t)(i + 1) * H1 + head];
        float a2 = g_alpha1[(size_t)(i + 2) * H1 + head];
        float a3 = g_alpha1[(size_t)(i + 3) * H1 + head];
        uint2 u0 = *reinterpret_cast<const uint2*>(g_h1h + (size_t)s0 * F1 + c);
        uint2 u1 = *reinterpret_cast<const uint2*>(g_h1h + (size_t)s1 * F1 + c);
        uint2 u2 = *reinterpret_cast<const uint2*>(g_h1h + (size_t)s2 * F1 + c);
        uint2 u3 = *reinterpret_cast<const uint2*>(g_h1h + (size_t)s3 * F1 + c);
        float2 p0a = __half22float2(*reinterpret_cast<__half2*>(&u0.x));
        float2 p0b = __half22float2(*reinterpret_cast<__half2*>(&u0.y));
        float2 p1a = __half22float2(*reinterpret_cast<__half2*>(&u1.x));
        float2 p1b = __half22float2(*reinterpret_cast<__half2*>(&u1.y));
        float2 p2a = __half22float2(*reinterpret_cast<__half2*>(&u2.x));
        float2 p2b = __half22float2(*reinterpret_cast<__half2*>(&u2.y));
        float2 p3a = __half22float2(*reinterpret_cast<__half2*>(&u3.x));
        float2 p3b = __half22float2(*reinterpret_cast<__half2*>(&u3.y));
        acc.x += a0 * p0a.x + a1 * p1a.x + a2 * p2a.x + a3 * p3a.x;
        acc.y += a0 * p0a.y + a1 * p1a.y + a2 * p2a.y + a3 * p3a.y;
        acc.z += a0 * p0b.x + a1 * p1b.x + a2 * p2b.x + a3 * p3b.x;
        acc.w += a0 * p0b.y + a1 * p1b.y + a2 * p2b.y + a3 * p3b.y;
    }
    for (; i < end; i++) {
        int s = g_src[i];
        float a = g_alpha1[(size_t)i * H1 + head];
        uint2 u = *reinterpret_cast<const uint2*>(g_h1h + (size_t)s * F1 + c);
        float2 pa = __half22float2(*reinterpret_cast<__half2*>(&u.x));
        float2 pb = __half22float2(*reinterpret_cast<__half2*>(&u.y));
        acc.x += a * pa.x; acc.y += a * pa.y; acc.z += a * pb.x; acc.w += a * pb.y;
    }
    float rinv = 1.f / (g_dsum1[n * H1 + head] + 1e-16f);
    float4 bb = *reinterpret_cast<const float4*>(b1 + c);
    float4 o;
    o.x = __uint_as_float(f2tf32(leaky(acc.x * rinv + bb.x, 0.01f)));
    o.y = __uint_as_float(f2tf32(leaky(acc.y * rinv + bb.y, 0.01f)));
    o.z = __uint_as_float(f2tf32(leaky(acc.z * rinv + bb.z, 0.01f)));
    o.w = __uint_as_float(f2tf32(leaky(acc.w * rinv + bb.w, 0.01f)));
    *reinterpret_cast<float4*>(g_o1 + (size_t)n * F1 + c) = o;
}

// ---------------- layer-2 aggregation: bbox only ----------------------------
__global__ void k_agg2(const void* __restrict__ bbox, const float* __restrict__ b2,
                       float* __restrict__ out) {
    __shared__ float4 red[H2][32];
    int bi = blockIdx.x;
    int head = threadIdx.x >> 5;           // 0..2
    int lane = threadIdx.x & 31;
    int c = head * 128 + lane * 4;
    int n = load_idx(bbox, bi);
    int beg = g_off[n], end = g_off[n + 1];
    float4 acc = make_float4(0.f, 0.f, 0.f, 0.f);
    int e = beg;
    for (; e + 4 <= end; e += 4) {
        int s0 = g_src[e], s1 = g_src[e + 1], s2 = g_src[e + 2], s3 = g_src[e + 3];
        float a0 = g_alpha2[(size_t)(e    ) * H2 + head];
        float a1 = g_alpha2[(size_t)(e + 1) * H2 + head];
        float a2 = g_alpha2[(size_t)(e + 2) * H2 + head];
        float a3 = g_alpha2[(size_t)(e + 3) * H2 + head];
        float4 v0 = *reinterpret_cast<const float4*>(g_h2 + (size_t)s0 * F2 + c);
        float4 v1 = *reinterpret_cast<const float4*>(g_h2 + (size_t)s1 * F2 + c);
        float4 v2 = *reinterpret_cast<const float4*>(g_h2 + (size_t)s2 * F2 + c);
        float4 v3 = *reinterpret_cast<const float4*>(g_h2 + (size_t)s3 * F2 + c);
        acc.x += a0 * v0.x + a1 * v1.x + a2 * v2.x + a3 * v3.x;
        acc.y += a0 * v0.y + a1 * v1.y + a2 * v2.y + a3 * v3.y;
        acc.z += a0 * v0.z + a1 * v1.z + a2 * v2.z + a3 * v3.z;
        acc.w += a0 * v0.w + a1 * v1.w + a2 * v2.w + a3 * v3.w;
    }
    for (; e < end; e++) {
        int s = g_src[e];
        float a = g_alpha2[(size_t)e * H2 + head];
        float4 v = *reinterpret_cast<const float4*>(g_h2 + (size_t)s * F2 + c);
        acc.x += a * v.x; acc.y += a * v.y; acc.z += a * v.z; acc.w += a * v.w;
    }
    float rinv = 1.f / (g_dsum2[n * H2 + head] + 1e-16f);
    acc.x *= rinv; acc.y *= rinv; acc.z *= rinv; acc.w *= rinv;
    red[head][lane] = acc;
    __syncthreads();
    if (head == 0) {
        float4 r0 = red[0][lane], r1 = red[1][lane], r2 = red[2][lane];
        float4 bb = *reinterpret_cast<const float4*>(b2 + lane * 4);
        float4 o;
        o.x = leaky((r0.x + r1.x + r2.x) * (1.f / 3.f) + bb.x, 0.01f);
        o.y = leaky((r0.y + r1.y + r2.y) * (1.f / 3.f) + bb.y, 0.01f);
        o.z = leaky((r0.z + r1.z + r2.z) * (1.f / 3.f) + bb.z, 0.01f);
        o.w = leaky((r0.w + r1.w + r2.w) * (1.f / 3.f) + bb.w, 0.01f);
        *reinterpret_cast<float4*>(out + (size_t)bi * 128 + lane * 4) = o;
    }
}

// ---------------- launch ----------------------------------------------------
extern "C" void kernel_launch(void* const* d_in, const int* in_sizes, int n_in,
                              void* d_out, int out_size) {
    const float *x = nullptr, *W1 = nullptr, *W2 = nullptr, *b1 = nullptr, *b2 = nullptr;
    const float *att_src1 = nullptr, *att_dst1 = nullptr;
    const float *att_src2 = nullptr, *att_dst2 = nullptr;
    const void *ei = nullptr, *bbox = nullptr;
    int n640 = 0, n384 = 0;
    for (int i = 0; i < n_in; i++) {
        switch (in_sizes[i]) {
            case N_NODES * GCN_IN: x    = (const float*)d_in[i]; break;
            case 2 * N_EDGES:      ei   = d_in[i]; break;
            case N_BBOX:           bbox = d_in[i]; break;
            case GCN_IN * F1:      W1   = (const float*)d_in[i]; break;
            case F1 * F2:          W2   = (const float*)d_in[i]; break;
            case C2:               b2   = (const float*)d_in[i]; break;
            case F1:
                if      (n640 == 0) att_src1 = (const float*)d_in[i];
                else if (n640 == 1) att_dst1 = (const float*)d_in[i];
                else                b1       = (const float*)d_in[i];
                n640++; break;
            case F2:
                if (n384 == 0) att_src2 = (const float*)d_in[i];
                else           att_dst2 = (const float*)d_in[i];
                n384++; break;
            default: break;
        }
    }
    float* out = (float*)d_out;

    float *xr, *w1t, *w2t, *as1, *ad1, *as2, *ad2, *al1, *al2, *ds1, *ds2;
    cudaGetSymbolAddress((void**)&xr,  g_xr);
    cudaGetSymbolAddress((void**)&w1t, g_w1t);
    cudaGetSymbolAddress((void**)&w2t, g_w2t);
    cudaGetSymbolAddress((void**)&as1, g_as1);
    cudaGetSymbolAddress((void**)&ad1, g_ad1);
    cudaGetSymbolAddress((void**)&as2, g_as2);
    cudaGetSymbolAddress((void**)&ad2, g_ad2);
    cudaGetSymbolAddress((void**)&al1, g_alpha1);
    cudaGetSymbolAddress((void**)&al2, g_alpha2);
    cudaGetSymbolAddress((void**)&ds1, g_dsum1);
    cudaGetSymbolAddress((void**)&ds2, g_dsum2);

    cudaFuncSetAttribute(gemm_tf32<0>, cudaFuncAttributeMaxDynamicSharedMemorySize, GEMM_SMEM);
    cudaFuncSetAttribute(gemm_tf32<1>, cudaFuncAttributeMaxDynamicSharedMemorySize, GEMM_SMEM);

    k_detect<<<1, 1>>>(ei);
    k_round<<<(N_NODES * GCN_IN / 4 + 255) / 256, 256>>>(x, xr, N_NODES * GCN_IN / 4);
    k_transpose<<<dim3(F1 / 32, GCN_IN / 32), dim3(32, 8)>>>(W1, w1t, GCN_IN, F1);
    {   // profiled slot
        dim3 g(F1 / GBN, (N_NODES + GBM - 1) / GBM);
        gemm_tf32<0><<<g, 256, GEMM_SMEM>>>(att_src1, att_dst1);
    }
    k_transpose<<<dim3(F2 / 32, F1 / 32), dim3(32, 8)>>>(W2, w2t, F1, F2);
    k_zero<<<(N_NODES * H1 + 255) / 256, 256>>>();
    k_hist<<<(ET + 255) / 256, 256>>>(ei);
    k_scan1<<<NB_SCAN, 1024>>>();
    k_scan2<<<1, 32>>>();
    k_scan3<<<NB_SCAN, 1024>>>();
    k_scatter<<<(ET + 255) / 256, 256>>>(ei);

    k_sm_edges<H1><<<(ET + 255) / 256, 256>>>(as1, ad1, al1, ds1);
    k_agg1<<<N_NODES, H1 * 32>>>(b1);

    {
        dim3 g(F2 / GBN, (N_NODES + GBM - 1) / GBM);
        gemm_tf32<1><<<g, 256, GEMM_SMEM>>>(att_src2, att_dst2);
    }
    k_sm_edges<H2><<<(ET + 255) / 256, 256>>>(as2, ad2, al2, ds2);
    k_agg2<<<N_BBOX, H2 * 32>>>(bbox, b2, out);
}

// round 10
// speedup vs baseline: 1.0640x; 1.0640x over previous
#include <cuda_runtime.h>
#include <cuda_fp16.h>
#include <cstdint>

#define N_NODES 20000
#define N_EDGES 320000
#define ET      (N_EDGES + N_NODES)   // 340000
#define GCN_IN  256
#define C1      128
#define H1      5
#define F1      (H1*C1)               // 640
#define C2      128
#define H2      3
#define F2      (H2*C2)               // 384
#define N_BBOX  4096
#define NB_SCAN ((N_NODES + 1023) / 1024)   // 20

// ---------------- scratch ---------------------------------------------------
__device__ int    g_is64;
__device__ int    g_cnt[N_NODES];
__device__ int    g_cur[N_NODES];
__device__ int    g_claim[N_NODES];
__device__ int    g_off[N_NODES + 1];
__device__ int    g_src[ET];
__device__ int    g_bsum[32];
__device__ int    g_bpre[32];
__device__ float  g_xr[(size_t)N_NODES * GCN_IN];   // tf32-rounded x
__device__ float  g_w1t[F1 * GCN_IN];               // W1^T tf32 [F1][256]
__device__ float  g_w2t[F2 * F1];                   // W2^T tf32 [F2][640]
__device__ __half g_h1h[(size_t)N_NODES * F1];      // h1 fp16 mirror (gather-only)
__device__ __half g_h2h[(size_t)N_NODES * F2];      // h2 fp16 mirror (gather-only)
__device__ float  g_o1[(size_t)N_NODES * F1];       // layer1 out, tf32-rounded
__device__ float  g_as1[N_NODES * H1];
__device__ float  g_ad1[N_NODES * H1];
__device__ float  g_as2[N_NODES * H2];
__device__ float  g_ad2[N_NODES * H2];
__device__ float  g_rinv1[N_NODES * H1];
__device__ float  g_rinv2[N_NODES * H2];
__device__ float  g_alpha1[(size_t)ET * H1];
__device__ float  g_alpha2[(size_t)ET * H2];

__device__ __forceinline__ float leaky(float x, float s) {
    return x >= 0.f ? x : s * x;
}
__device__ __forceinline__ int load_idx(const void* p, long long i) {
    return g_is64 ? (int)((const long long*)p)[i] : ((const int*)p)[i];
}
__device__ __forceinline__ uint32_t f2tf32(float x) {
    uint32_t u;
    asm("cvt.rna.tf32.f32 %0, %1;" : "=r"(u) : "f"(x));
    return u;
}
__device__ __forceinline__ void ldm_x4(uint32_t (&r)[4], uint32_t addr) {
    asm volatile("ldmatrix.sync.aligned.m8n8.x4.shared.b16 {%0,%1,%2,%3}, [%4];"
                 : "=r"(r[0]), "=r"(r[1]), "=r"(r[2]), "=r"(r[3]) : "r"(addr));
}

// ---------------- dtype sniff -----------------------------------------------
__global__ void k_detect(const void* ei) {
    const int* p = (const int*)ei;
    int nz = 0;
    #pragma unroll
    for (int i = 0; i < 64; i++) nz |= p[2 * i + 1];
    g_is64 = (nz == 0) ? 1 : 0;
}

// ---------------- tf32 pre-round (float4) -----------------------------------
__global__ void k_round(const float* __restrict__ in, float* __restrict__ out, int n4) {
    int i = blockIdx.x * blockDim.x + threadIdx.x;
    if (i >= n4) return;
    float4 v = reinterpret_cast<const float4*>(in)[i];
    v.x = __uint_as_float(f2tf32(v.x));
    v.y = __uint_as_float(f2tf32(v.y));
    v.z = __uint_as_float(f2tf32(v.z));
    v.w = __uint_as_float(f2tf32(v.w));
    reinterpret_cast<float4*>(out)[i] = v;
}

// ---------------- transpose + round: W[K][N] -> Wt[N][K] --------------------
__global__ void k_transpose(const float* __restrict__ in, float* __restrict__ out,
                            int K, int N) {
    __shared__ float tile[32][33];
    int n0 = blockIdx.x * 32, k0 = blockIdx.y * 32;
    int tx = threadIdx.x, ty = threadIdx.y;
    #pragma unroll
    for (int j = 0; j < 32; j += 8)
        tile[ty + j][tx] = in[(size_t)(k0 + ty + j) * N + n0 + tx];
    __syncthreads();
    #pragma unroll
    for (int j = 0; j < 32; j += 8)
        out[(size_t)(n0 + ty + j) * K + k0 + tx] =
            __uint_as_float(f2tf32(tile[tx][ty + j]));
}

// ---------------- CSR build -------------------------------------------------
__global__ void k_zero() {
    int i = blockIdx.x * blockDim.x + threadIdx.x;
    if (i < N_NODES) { g_cnt[i] = 0; g_cur[i] = 0; g_claim[i] = 0; }
}

__global__ void k_hist(const void* __restrict__ ei) {
    int e = blockIdx.x * blockDim.x + threadIdx.x;
    if (e >= ET) return;
    int dst = (e < N_EDGES) ? load_idx(ei, (long long)N_EDGES + e) : (e - N_EDGES);
    atomicAdd(&g_cnt[dst], 1);
}

__global__ void k_scan1() {
    __shared__ int ws[32];
    int tid = threadIdx.x, lane = tid & 31, wid = tid >> 5;
    int i = blockIdx.x * 1024 + tid;
    int v = (i < N_NODES) ? g_cnt[i] : 0;
    int x = v;
    #pragma unroll
    for (int o = 1; o < 32; o <<= 1) {
        int y = __shfl_up_sync(~0u, x, o);
        if (lane >= o) x += y;
    }
    if (lane == 31) ws[wid] = x;
    __syncthreads();
    if (wid == 0) {
        int w = ws[lane];
        #pragma unroll
        for (int o = 1; o < 32; o <<= 1) {
            int y = __shfl_up_sync(~0u, w, o);
            if (lane >= o) w += y;
        }
        ws[lane] = w;
    }
    __syncthreads();
    int incl = x + (wid > 0 ? ws[wid - 1] : 0);
    if (i < N_NODES) g_off[i + 1] = incl;
    if (tid == 1023) g_bsum[blockIdx.x] = incl;
}

__global__ void k_scan2() {
    int lane = threadIdx.x;
    int v = (lane < NB_SCAN) ? g_bsum[lane] : 0;
    int x = v;
    #pragma unroll
    for (int o = 1; o < 32; o <<= 1) {
        int y = __shfl_up_sync(~0u, x, o);
        if (lane >= o) x += y;
    }
    g_bpre[lane] = x - v;
}

__global__ void k_scan3() {
    int i = blockIdx.x * 1024 + threadIdx.x;
    if (i == 0) g_off[0] = 0;
    if (i < N_NODES) g_off[i + 1] += g_bpre[blockIdx.x];
}

__global__ void k_scatter(const void* __restrict__ ei) {
    int e = blockIdx.x * blockDim.x + threadIdx.x;
    if (e >= ET) return;
    int src, dst;
    if (e < N_EDGES) {
        src = load_idx(ei, e);
        dst = load_idx(ei, (long long)N_EDGES + e);
    } else {
        src = dst = e - N_EDGES;
    }
    int p = g_off[dst] + atomicAdd(&g_cur[dst], 1);
    g_src[p] = src;
}

// ---------------- TF32 GEMM: ldmatrix + fused attention dots ----------------
// Both layers store C as fp16 mirror (gather-only consumers).
#define GBM 128
#define GBN 128
#define GBK 16
#define SA  20
#define SBK 20
#define STG 3
#define GEMM_SMEM (STG * (GBM * SA + GBN * SBK) * 4)

template<int MODE>
__global__ void __launch_bounds__(256, 2)
gemm_tf32(const float* __restrict__ asrc, const float* __restrict__ adst) {
    const int M = N_NODES;
    const int K = (MODE == 0) ? GCN_IN : F1;
    const int N = (MODE == 0) ? F1 : F2;
    const int H = (MODE == 0) ? H1 : H2;
    const float* A  = (MODE == 0) ? (const float*)g_xr  : (const float*)g_o1;
    const float* Bt = (MODE == 0) ? (const float*)g_w1t : (const float*)g_w2t;
    __half* Ch = (MODE == 0) ? g_h1h : g_h2h;
    float* oas = (MODE == 0) ? g_as1 : g_as2;
    float* oad = (MODE == 0) ? g_ad1 : g_ad2;

    extern __shared__ float smem[];
    float* As = smem;                        // [STG][GBM*SA]
    float* Bs = smem + STG * GBM * SA;       // [STG][GBN*SBK]
    __shared__ float red_s[GBM], red_d[GBM];

    int tid = threadIdx.x, lane = tid & 31, warp = tid >> 5;
    int warp_m = (warp & 3) * 32;
    int warp_n = (warp >> 2) * 64;
    int head = blockIdx.x;
    int rb = blockIdx.y * GBM, cb = head * GBN;
    int grp = lane >> 2, sub = lane & 3;

    const int arow = tid >> 2;
    const int acol = (tid & 3) * 4;
    const int brow = tid >> 2;
    const int bcol = (tid & 3) * 4;

    uint32_t sAb = (uint32_t)__cvta_generic_to_shared(As);
    uint32_t sBb = (uint32_t)__cvta_generic_to_shared(Bs);
    uint32_t aoff = sAb + (((lane & 15) + warp_m) * SA + ((lane >> 4) << 2)) * 4;
    uint32_t boff = sBb + (((lane & 15) + warp_n) * SBK + ((lane >> 4) << 2)) * 4;

    float acc[2][8][4];
    #pragma unroll
    for (int i = 0; i < 2; i++)
        #pragma unroll
        for (int j = 0; j < 8; j++)
            #pragma unroll
            for (int q = 0; q < 4; q++) acc[i][j][q] = 0.f;

    auto copy_tile = [&](int t, int buf) {
        int k0 = t * GBK;
        float* Ab = As + buf * GBM * SA;
        float* Bb = Bs + buf * GBN * SBK;
        #pragma unroll
        for (int p = 0; p < 2; p++) {
            int r = p * 64 + arow;
            const float* src = A + (size_t)(rb + r) * K + k0 + acol;
            uint32_t dst = (uint32_t)__cvta_generic_to_shared(&Ab[r * SA + acol]);
            int sz = (rb + r < M) ? 16 : 0;
            asm volatile("cp.async.cg.shared.global [%0], [%1], 16, %2;\n"
                         :: "r"(dst), "l"(src), "r"(sz));
        }
        #pragma unroll
        for (int p = 0; p < 2; p++) {
            int r = p * 64 + brow;
            const float* src = Bt + (size_t)(cb + r) * K + k0 + bcol;
            uint32_t dst = (uint32_t)__cvta_generic_to_shared(&Bb[r * SBK + bcol]);
            asm volatile("cp.async.cg.shared.global [%0], [%1], 16;\n"
                         :: "r"(dst), "l"(src));
        }
        asm volatile("cp.async.commit_group;\n" ::: "memory");
    };

    const int T = K / GBK;
    copy_tile(0, 0);
    copy_tile(1, 1);

    for (int t = 0; t < T; t++) {
        if (t < T - 1)
            asm volatile("cp.async.wait_group 1;\n" ::: "memory");
        else
            asm volatile("cp.async.wait_group 0;\n" ::: "memory");
        __syncthreads();
        if (t + 2 < T) copy_tile(t + 2, (t + 2) % STG);

        int buf = t % STG;
        uint32_t aB = aoff + buf * (GBM * SA * 4);
        uint32_t bB = boff + buf * (GBN * SBK * 4);

        #pragma unroll
        for (int kk = 0; kk < 2; kk++) {
            uint32_t a0[4], a1[4];
            ldm_x4(a0, aB + kk * 32);
            ldm_x4(a1, aB + kk * 32 + 16 * SA * 4);
            #pragma unroll
            for (int nt2 = 0; nt2 < 4; nt2++) {
                uint32_t b[4];
                ldm_x4(b, bB + kk * 32 + nt2 * (16 * SBK * 4));
                #pragma unroll
                for (int mt = 0; mt < 2; mt++) {
                    const uint32_t* a = (mt == 0) ? a0 : a1;
                    asm volatile(
                        "mma.sync.aligned.m16n8k8.row.col.f32.tf32.tf32.f32 "
                        "{%0,%1,%2,%3}, {%4,%5,%6,%7}, {%8,%9}, {%0,%1,%2,%3};"
                        : "+f"(acc[mt][2 * nt2][0]), "+f"(acc[mt][2 * nt2][1]),
                          "+f"(acc[mt][2 * nt2][2]), "+f"(acc[mt][2 * nt2][3])
                        : "r"(a[0]), "r"(a[1]), "r"(a[2]), "r"(a[3]),
                          "r"(b[0]), "r"(b[2]));
                    asm volatile(
                        "mma.sync.aligned.m16n8k8.row.col.f32.tf32.tf32.f32 "
                        "{%0,%1,%2,%3}, {%4,%5,%6,%7}, {%8,%9}, {%0,%1,%2,%3};"
                        : "+f"(acc[mt][2 * nt2 + 1][0]), "+f"(acc[mt][2 * nt2 + 1][1]),
                          "+f"(acc[mt][2 * nt2 + 1][2]), "+f"(acc[mt][2 * nt2 + 1][3])
                        : "r"(a[0]), "r"(a[1]), "r"(a[2]), "r"(a[3]),
                          "r"(b[1]), "r"(b[3]));
                }
            }
        }
    }

    // ---- store C as fp16 ----
    #pragma unroll
    for (int mt = 0; mt < 2; mt++) {
        int r0 = rb + warp_m + mt * 16 + grp;
        #pragma unroll
        for (int nt = 0; nt < 8; nt++) {
            int c0 = cb + warp_n + nt * 8 + 2 * sub;
            if (r0 < M)
                *reinterpret_cast<__half2*>(Ch + (size_t)r0 * N + c0) =
                    __floats2half2_rn(acc[mt][nt][0], acc[mt][nt][1]);
            if (r0 + 8 < M)
                *reinterpret_cast<__half2*>(Ch + (size_t)(r0 + 8) * N + c0) =
                    __floats2half2_rn(acc[mt][nt][2], acc[mt][nt][3]);
        }
    }

    // ---- fused attention dots (fp32 accumulators) ----
    float ps[2][2] = {{0.f, 0.f}, {0.f, 0.f}};
    float pd[2][2] = {{0.f, 0.f}, {0.f, 0.f}};
    #pragma unroll
    for (int nt = 0; nt < 8; nt++) {
        int cc = warp_n + nt * 8 + 2 * sub;
        float s0 = asrc[head * 128 + cc],     d0 = adst[head * 128 + cc];
        float s1 = asrc[head * 128 + cc + 1], d1 = adst[head * 128 + cc + 1];
        #pragma unroll
        for (int mt = 0; mt < 2; mt++) {
            ps[mt][0] += acc[mt][nt][0] * s0 + acc[mt][nt][1] * s1;
            pd[mt][0] += acc[mt][nt][0] * d0 + acc[mt][nt][1] * d1;
            ps[mt][1] += acc[mt][nt][2] * s0 + acc[mt][nt][3] * s1;
            pd[mt][1] += acc[mt][nt][2] * d0 + acc[mt][nt][3] * d1;
        }
    }
    #pragma unroll
    for (int mt = 0; mt < 2; mt++)
        #pragma unroll
        for (int hf = 0; hf < 2; hf++) {
            #pragma unroll
            for (int o = 1; o < 4; o <<= 1) {
                ps[mt][hf] += __shfl_xor_sync(~0u, ps[mt][hf], o);
                pd[mt][hf] += __shfl_xor_sync(~0u, pd[mt][hf], o);
            }
        }
    if (warp >= 4 && sub == 0) {
        #pragma unroll
        for (int mt = 0; mt < 2; mt++)
            #pragma unroll
            for (int hf = 0; hf < 2; hf++) {
                int lr = warp_m + mt * 16 + hf * 8 + grp;
                red_s[lr] = ps[mt][hf];
                red_d[lr] = pd[mt][hf];
            }
    }
    __syncthreads();
    if (warp < 4 && sub == 0) {
        #pragma unroll
        for (int mt = 0; mt < 2; mt++)
            #pragma unroll
            for (int hf = 0; hf < 2; hf++) {
                int lr = warp_m + mt * 16 + hf * 8 + grp;
                int r = rb + lr;
                if (r < M) {
                    oas[r * H + head] = ps[mt][hf] + red_s[lr];
                    oad[r * H + head] = pd[mt][hf] + red_d[lr];
                }
            }
    }
}

// ---------------- segment softmax: store exp + 1/denom ----------------------
template<int H>
__device__ __forceinline__ void softmax_node(int n, const float* as_, const float* ad_,
                                             float* alpha, float* rinvg, int lane) {
    int beg = g_off[n], end = g_off[n + 1];
    float ad[H], m[H], dsum[H];
    #pragma unroll
    for (int h = 0; h < H; h++) { ad[h] = ad_[n * H + h]; m[h] = -1e30f; dsum[h] = 0.f; }
    for (int i = beg + lane; i < end; i += 32) {
        int s = g_src[i];
        #pragma unroll
        for (int h = 0; h < H; h++) {
            float e = leaky(as_[s * H + h] + ad[h], 0.2f);
            alpha[(size_t)i * H + h] = e;
            m[h] = fmaxf(m[h], e);
        }
    }
    #pragma unroll
    for (int h = 0; h < H; h++)
        #pragma unroll
        for (int o = 16; o; o >>= 1) m[h] = fmaxf(m[h], __shfl_xor_sync(~0u, m[h], o));
    for (int i = beg + lane; i < end; i += 32) {
        #pragma unroll
        for (int h = 0; h < H; h++) {
            float ex = expf(alpha[(size_t)i * H + h] - m[h]);
            alpha[(size_t)i * H + h] = ex;
            dsum[h] += ex;
        }
    }
    #pragma unroll
    for (int h = 0; h < H; h++)
        #pragma unroll
        for (int o = 16; o; o >>= 1) dsum[h] += __shfl_xor_sync(~0u, dsum[h], o);
    if (lane == 0)
        #pragma unroll
        for (int h = 0; h < H; h++) rinvg[n * H + h] = 1.f / (dsum[h] + 1e-16f);
}

__global__ void k_softmax1() {
    int n = (blockIdx.x * blockDim.x + threadIdx.x) >> 5;
    int lane = threadIdx.x & 31;
    if (n >= N_NODES) return;
    softmax_node<H1>(n, g_as1, g_ad1, g_alpha1, g_rinv1, lane);
}

__global__ void k_softmax2(const void* __restrict__ bbox) {
    int wi = (blockIdx.x * blockDim.x + threadIdx.x) >> 5;
    int lane = threadIdx.x & 31;
    if (wi >= N_BBOX) return;
    int n = load_idx(bbox, wi);
    int claimed = 0;
    if (lane == 0) claimed = atomicExch(&g_claim[n], 1);
    claimed = __shfl_sync(~0u, claimed, 0);
    if (claimed) return;
    softmax_node<H2>(n, g_as2, g_ad2, g_alpha2, g_rinv2, lane);
}

// ---------------- layer-1 aggregation: warp-per-head, fp16 gather -----------
__global__ void k_agg1(const float* __restrict__ b1) {
    int n = blockIdx.x;
    int head = threadIdx.x >> 5;           // 0..4
    int lane = threadIdx.x & 31;
    int c = head * 128 + lane * 4;
    int beg = g_off[n], end = g_off[n + 1];
    float4 acc = make_float4(0.f, 0.f, 0.f, 0.f);
    int i = beg;
    for (; i + 4 <= end; i += 4) {
        int s0 = g_src[i], s1 = g_src[i + 1], s2 = g_src[i + 2], s3 = g_src[i + 3];
        float a0 = g_alpha1[(size_t)(i    ) * H1 + head];
        float a1 = g_alpha1[(size_t)(i + 1) * H1 + head];
        float a2 = g_alpha1[(size_t)(i + 2) * H1 + head];
        float a3 = g_alpha1[(size_t)(i + 3) * H1 + head];
        uint2 u0 = *reinterpret_cast<const uint2*>(g_h1h + (size_t)s0 * F1 + c);
        uint2 u1 = *reinterpret_cast<const uint2*>(g_h1h + (size_t)s1 * F1 + c);
        uint2 u2 = *reinterpret_cast<const uint2*>(g_h1h + (size_t)s2 * F1 + c);
        uint2 u3 = *reinterpret_cast<const uint2*>(g_h1h + (size_t)s3 * F1 + c);
        float2 p0a = __half22float2(*reinterpret_cast<__half2*>(&u0.x));
        float2 p0b = __half22float2(*reinterpret_cast<__half2*>(&u0.y));
        float2 p1a = __half22float2(*reinterpret_cast<__half2*>(&u1.x));
        float2 p1b = __half22float2(*reinterpret_cast<__half2*>(&u1.y));
        float2 p2a = __half22float2(*reinterpret_cast<__half2*>(&u2.x));
        float2 p2b = __half22float2(*reinterpret_cast<__half2*>(&u2.y));
        float2 p3a = __half22float2(*reinterpret_cast<__half2*>(&u3.x));
        float2 p3b = __half22float2(*reinterpret_cast<__half2*>(&u3.y));
        acc.x += a0 * p0a.x + a1 * p1a.x + a2 * p2a.x + a3 * p3a.x;
        acc.y += a0 * p0a.y + a1 * p1a.y + a2 * p2a.y + a3 * p3a.y;
        acc.z += a0 * p0b.x + a1 * p1b.x + a2 * p2b.x + a3 * p3b.x;
        acc.w += a0 * p0b.y + a1 * p1b.y + a2 * p2b.y + a3 * p3b.y;
    }
    for (; i < end; i++) {
        int s = g_src[i];
        float a = g_alpha1[(size_t)i * H1 + head];
        uint2 u = *reinterpret_cast<const uint2*>(g_h1h + (size_t)s * F1 + c);
        float2 pa = __half22float2(*reinterpret_cast<__half2*>(&u.x));
        float2 pb = __half22float2(*reinterpret_cast<__half2*>(&u.y));
        acc.x += a * pa.x; acc.y += a * pa.y; acc.z += a * pb.x; acc.w += a * pb.y;
    }
    float rinv = g_rinv1[n * H1 + head];
    float4 bb = *reinterpret_cast<const float4*>(b1 + c);
    float4 o;
    o.x = __uint_as_float(f2tf32(leaky(acc.x * rinv + bb.x, 0.01f)));
    o.y = __uint_as_float(f2tf32(leaky(acc.y * rinv + bb.y, 0.01f)));
    o.z = __uint_as_float(f2tf32(leaky(acc.z * rinv + bb.z, 0.01f)));
    o.w = __uint_as_float(f2tf32(leaky(acc.w * rinv + bb.w, 0.01f)));
    *reinterpret_cast<float4*>(g_o1 + (size_t)n * F1 + c) = o;
}

// ---------------- layer-2 aggregation: bbox only, fp16 gather ---------------
__global__ void k_agg2(const void* __restrict__ bbox, const float* __restrict__ b2,
                       float* __restrict__ out) {
    __shared__ float4 red[H2][32];
    int bi = blockIdx.x;
    int head = threadIdx.x >> 5;           // 0..2
    int lane = threadIdx.x & 31;
    int c = head * 128 + lane * 4;
    int n = load_idx(bbox, bi);
    int beg = g_off[n], end = g_off[n + 1];
    float4 acc = make_float4(0.f, 0.f, 0.f, 0.f);
    int e = beg;
    for (; e + 4 <= end; e += 4) {
        int s0 = g_src[e], s1 = g_src[e + 1], s2 = g_src[e + 2], s3 = g_src[e + 3];
        float a0 = g_alpha2[(size_t)(e    ) * H2 + head];
        float a1 = g_alpha2[(size_t)(e + 1) * H2 + head];
        float a2 = g_alpha2[(size_t)(e + 2) * H2 + head];
        float a3 = g_alpha2[(size_t)(e + 3) * H2 + head];
        uint2 u0 = *reinterpret_cast<const uint2*>(g_h2h + (size_t)s0 * F2 + c);
        uint2 u1 = *reinterpret_cast<const uint2*>(g_h2h + (size_t)s1 * F2 + c);
        uint2 u2 = *reinterpret_cast<const uint2*>(g_h2h + (size_t)s2 * F2 + c);
        uint2 u3 = *reinterpret_cast<const uint2*>(g_h2h + (size_t)s3 * F2 + c);
        float2 p0a = __half22float2(*reinterpret_cast<__half2*>(&u0.x));
        float2 p0b = __half22float2(*reinterpret_cast<__half2*>(&u0.y));
        float2 p1a = __half22float2(*reinterpret_cast<__half2*>(&u1.x));
        float2 p1b = __half22float2(*reinterpret_cast<__half2*>(&u1.y));
        float2 p2a = __half22float2(*reinterpret_cast<__half2*>(&u2.x));
        float2 p2b = __half22float2(*reinterpret_cast<__half2*>(&u2.y));
        float2 p3a = __half22float2(*reinterpret_cast<__half2*>(&u3.x));
        float2 p3b = __half22float2(*reinterpret_cast<__half2*>(&u3.y));
        acc.x += a0 * p0a.x + a1 * p1a.x + a2 * p2a.x + a3 * p3a.x;
        acc.y += a0 * p0a.y + a1 * p1a.y + a2 * p2a.y + a3 * p3a.y;
        acc.z += a0 * p0b.x + a1 * p1b.x + a2 * p2b.x + a3 * p3b.x;
        acc.w += a0 * p0b.y + a1 * p1b.y + a2 * p2b.y + a3 * p3b.y;
    }
    for (; e < end; e++) {
        int s = g_src[e];
        float a = g_alpha2[(size_t)e * H2 + head];
        uint2 u = *reinterpret_cast<const uint2*>(g_h2h + (size_t)s * F2 + c);
        float2 pa = __half22float2(*reinterpret_cast<__half2*>(&u.x));
        float2 pb = __half22float2(*reinterpret_cast<__half2*>(&u.y));
        acc.x += a * pa.x; acc.y += a * pa.y; acc.z += a * pb.x; acc.w += a * pb.y;
    }
    float rinv = g_rinv2[n * H2 + head];
    acc.x *= rinv; acc.y *= rinv; acc.z *= rinv; acc.w *= rinv;
    red[head][lane] = acc;
    __syncthreads();
    if (head == 0) {
        float4 r0 = red[0][lane], r1 = red[1][lane], r2 = red[2][lane];
        float4 bb = *reinterpret_cast<const float4*>(b2 + lane * 4);
        float4 o;
        o.x = leaky((r0.x + r1.x + r2.x) * (1.f / 3.f) + bb.x, 0.01f);
        o.y = leaky((r0.y + r1.y + r2.y) * (1.f / 3.f) + bb.y, 0.01f);
        o.z = leaky((r0.z + r1.z + r2.z) * (1.f / 3.f) + bb.z, 0.01f);
        o.w = leaky((r0.w + r1.w + r2.w) * (1.f / 3.f) + bb.w, 0.01f);
        *reinterpret_cast<float4*>(out + (size_t)bi * 128 + lane * 4) = o;
    }
}

// ---------------- launch ----------------------------------------------------
extern "C" void kernel_launch(void* const* d_in, const int* in_sizes, int n_in,
                              void* d_out, int out_size) {
    const float *x = nullptr, *W1 = nullptr, *W2 = nullptr, *b1 = nullptr, *b2 = nullptr;
    const float *att_src1 = nullptr, *att_dst1 = nullptr;
    const float *att_src2 = nullptr, *att_dst2 = nullptr;
    const void *ei = nullptr, *bbox = nullptr;
    int n640 = 0, n384 = 0;
    for (int i = 0; i < n_in; i++) {
        switch (in_sizes[i]) {
            case N_NODES * GCN_IN: x    = (const float*)d_in[i]; break;
            case 2 * N_EDGES:      ei   = d_in[i]; break;
            case N_BBOX:           bbox = d_in[i]; break;
            case GCN_IN * F1:      W1   = (const float*)d_in[i]; break;
            case F1 * F2:          W2   = (const float*)d_in[i]; break;
            case C2:               b2   = (const float*)d_in[i]; break;
            case F1:
                if      (n640 == 0) att_src1 = (const float*)d_in[i];
                else if (n640 == 1) att_dst1 = (const float*)d_in[i];
                else                b1       = (const float*)d_in[i];
                n640++; break;
            case F2:
                if (n384 == 0) att_src2 = (const float*)d_in[i];
                else           att_dst2 = (const float*)d_in[i];
                n384++; break;
            default: break;
        }
    }
    float* out = (float*)d_out;

    float *xr, *w1t, *w2t;
    cudaGetSymbolAddress((void**)&xr,  g_xr);
    cudaGetSymbolAddress((void**)&w1t, g_w1t);
    cudaGetSymbolAddress((void**)&w2t, g_w2t);

    cudaFuncSetAttribute(gemm_tf32<0>, cudaFuncAttributeMaxDynamicSharedMemorySize, GEMM_SMEM);
    cudaFuncSetAttribute(gemm_tf32<1>, cudaFuncAttributeMaxDynamicSharedMemorySize, GEMM_SMEM);

    k_detect<<<1, 1>>>(ei);
    k_round<<<(N_NODES * GCN_IN / 4 + 255) / 256, 256>>>(x, xr, N_NODES * GCN_IN / 4);
    k_transpose<<<dim3(F1 / 32, GCN_IN / 32), dim3(32, 8)>>>(W1, w1t, GCN_IN, F1);
    {   // profiled slot
        dim3 g(F1 / GBN, (N_NODES + GBM - 1) / GBM);
        gemm_tf32<0><<<g, 256, GEMM_SMEM>>>(att_src1, att_dst1);
    }
    k_transpose<<<dim3(F2 / 32, F1 / 32), dim3(32, 8)>>>(W2, w2t, F1, F2);
    k_zero<<<(N_NODES + 255) / 256, 256>>>();
    k_hist<<<(ET + 255) / 256, 256>>>(ei);
    k_scan1<<<NB_SCAN, 1024>>>();
    k_scan2<<<1, 32>>>();
    k_scan3<<<NB_SCAN, 1024>>>();
    k_scatter<<<(ET + 255) / 256, 256>>>(ei);

    k_softmax1<<<(N_NODES * 32 + 255) / 256, 256>>>();
    k_agg1<<<N_NODES, H1 * 32>>>(b1);

    {
        dim3 g(F2 / GBN, (N_NODES + GBM - 1) / GBM);
        gemm_tf32<1><<<g, 256, GEMM_SMEM>>>(att_src2, att_dst2);
    }
    k_softmax2<<<(N_BBOX * 32 + 255) / 256, 256>>>(bbox);
    k_agg2<<<N_BBOX, H2 * 32>>>(bbox, b2, out);
}

// round 11
// speedup vs baseline: 1.3960x; 1.3120x over previous
#include <cuda_runtime.h>
#include <cuda_fp16.h>
#include <cstdint>

#define N_NODES 20000
#define N_EDGES 320000
#define ET      (N_EDGES + N_NODES)   // 340000
#define GCN_IN  256
#define C1      128
#define H1      5
#define F1      (H1*C1)               // 640
#define C2      128
#define H2      3
#define F2      (H2*C2)               // 384
#define N_BBOX  4096
#define NB_SCAN ((N_NODES + 1023) / 1024)   // 20

// ---------------- scratch ---------------------------------------------------
__device__ int    g_is64;
__device__ int    g_cnt[N_NODES];
__device__ int    g_cur[N_NODES];
__device__ int    g_claim[N_NODES];
__device__ int    g_off[N_NODES + 1];
__device__ int    g_src[ET];
__device__ int    g_bsum[32];
__device__ int    g_bpre[32];
__device__ __half g_xh[(size_t)N_NODES * GCN_IN];   // x as fp16
__device__ __half g_w1h[F1 * GCN_IN];               // W1^T fp16 [F1][256]
__device__ __half g_w2h[F2 * F1];                   // W2^T fp16 [F2][640]
__device__ __half g_h1h[(size_t)N_NODES * F1];      // h1 fp16 (gather-only)
__device__ __half g_h2h[(size_t)N_NODES * F2];      // h2 fp16 (gather-only)
__device__ __half g_o1h[(size_t)N_NODES * F1];      // layer1 out fp16 (gemm2 A)
__device__ float  g_as1[N_NODES * H1];
__device__ float  g_ad1[N_NODES * H1];
__device__ float  g_as2[N_NODES * H2];
__device__ float  g_ad2[N_NODES * H2];
__device__ float  g_rinv1[N_NODES * H1];
__device__ float  g_rinv2[N_NODES * H2];
__device__ float  g_alpha1[(size_t)ET * H1];
__device__ float  g_alpha2[(size_t)ET * H2];

__device__ __forceinline__ float leaky(float x, float s) {
    return x >= 0.f ? x : s * x;
}
__device__ __forceinline__ int load_idx(const void* p, long long i) {
    return g_is64 ? (int)((const long long*)p)[i] : ((const int*)p)[i];
}
__device__ __forceinline__ void ldm_x4(uint32_t (&r)[4], uint32_t addr) {
    asm volatile("ldmatrix.sync.aligned.m8n8.x4.shared.b16 {%0,%1,%2,%3}, [%4];"
                 : "=r"(r[0]), "=r"(r[1]), "=r"(r[2]), "=r"(r[3]) : "r"(addr));
}

// ---------------- dtype sniff -----------------------------------------------
__global__ void k_detect(const void* ei) {
    const int* p = (const int*)ei;
    int nz = 0;
    #pragma unroll
    for (int i = 0; i < 64; i++) nz |= p[2 * i + 1];
    g_is64 = (nz == 0) ? 1 : 0;
}

// ---------------- fp32 -> fp16 convert (8 elems/thread) ---------------------
__global__ void k_tohalf(const float* __restrict__ in, __half* __restrict__ out, int n8) {
    int i = blockIdx.x * blockDim.x + threadIdx.x;
    if (i >= n8) return;
    float4 v0 = reinterpret_cast<const float4*>(in)[2 * i];
    float4 v1 = reinterpret_cast<const float4*>(in)[2 * i + 1];
    __half2 h[4];
    h[0] = __floats2half2_rn(v0.x, v0.y);
    h[1] = __floats2half2_rn(v0.z, v0.w);
    h[2] = __floats2half2_rn(v1.x, v1.y);
    h[3] = __floats2half2_rn(v1.z, v1.w);
    reinterpret_cast<uint4*>(out)[i] = *reinterpret_cast<uint4*>(h);
}

// ---------------- transpose -> fp16: W[K][N] -> Wt[N][K] --------------------
__global__ void k_transpose_h(const float* __restrict__ in, __half* __restrict__ out,
                              int K, int N) {
    __shared__ float tile[32][33];
    int n0 = blockIdx.x * 32, k0 = blockIdx.y * 32;
    int tx = threadIdx.x, ty = threadIdx.y;
    #pragma unroll
    for (int j = 0; j < 32; j += 8)
        tile[ty + j][tx] = in[(size_t)(k0 + ty + j) * N + n0 + tx];
    __syncthreads();
    #pragma unroll
    for (int j = 0; j < 32; j += 8)
        out[(size_t)(n0 + ty + j) * K + k0 + tx] = __float2half(tile[tx][ty + j]);
}

// ---------------- CSR build -------------------------------------------------
__global__ void k_zero() {
    int i = blockIdx.x * blockDim.x + threadIdx.x;
    if (i < N_NODES) { g_cnt[i] = 0; g_cur[i] = 0; g_claim[i] = 0; }
}

__global__ void k_hist(const void* __restrict__ ei) {
    int e = blockIdx.x * blockDim.x + threadIdx.x;
    if (e >= ET) return;
    int dst = (e < N_EDGES) ? load_idx(ei, (long long)N_EDGES + e) : (e - N_EDGES);
    atomicAdd(&g_cnt[dst], 1);
}

__global__ void k_scan1() {
    __shared__ int ws[32];
    int tid = threadIdx.x, lane = tid & 31, wid = tid >> 5;
    int i = blockIdx.x * 1024 + tid;
    int v = (i < N_NODES) ? g_cnt[i] : 0;
    int x = v;
    #pragma unroll
    for (int o = 1; o < 32; o <<= 1) {
        int y = __shfl_up_sync(~0u, x, o);
        if (lane >= o) x += y;
    }
    if (lane == 31) ws[wid] = x;
    __syncthreads();
    if (wid == 0) {
        int w = ws[lane];
        #pragma unroll
        for (int o = 1; o < 32; o <<= 1) {
            int y = __shfl_up_sync(~0u, w, o);
            if (lane >= o) w += y;
        }
        ws[lane] = w;
    }
    __syncthreads();
    int incl = x + (wid > 0 ? ws[wid - 1] : 0);
    if (i < N_NODES) g_off[i + 1] = incl;
    if (tid == 1023) g_bsum[blockIdx.x] = incl;
}

__global__ void k_scan2() {
    int lane = threadIdx.x;
    int v = (lane < NB_SCAN) ? g_bsum[lane] : 0;
    int x = v;
    #pragma unroll
    for (int o = 1; o < 32; o <<= 1) {
        int y = __shfl_up_sync(~0u, x, o);
        if (lane >= o) x += y;
    }
    g_bpre[lane] = x - v;
}

__global__ void k_scan3() {
    int i = blockIdx.x * 1024 + threadIdx.x;
    if (i == 0) g_off[0] = 0;
    if (i < N_NODES) g_off[i + 1] += g_bpre[blockIdx.x];
}

__global__ void k_scatter(const void* __restrict__ ei) {
    int e = blockIdx.x * blockDim.x + threadIdx.x;
    if (e >= ET) return;
    int src, dst;
    if (e < N_EDGES) {
        src = load_idx(ei, e);
        dst = load_idx(ei, (long long)N_EDGES + e);
    } else {
        src = dst = e - N_EDGES;
    }
    int p = g_off[dst] + atomicAdd(&g_cur[dst], 1);
    g_src[p] = src;
}

// ---------------- FP16 GEMM (m16n8k16, fp32 accum) + fused attention --------
// C[M,N] = A[M,K] @ Bt[N,K]^T. GBN=128 = one head per CTA.
// BM=128 BN=128 BK=32(halves); 8 warps (4M x 2N), warp tile 32x64; 3-stage.
#define GBM 128
#define GBN 128
#define GBK 32
#define SAh 40
#define STG 3
#define STAGE_H (GBM * SAh)                 // halves per A (or B) stage
#define GEMM_SMEM (STG * 2 * STAGE_H * 2)   // bytes

template<int MODE>
__global__ void __launch_bounds__(256, 2)
gemm_f16(const float* __restrict__ asrc, const float* __restrict__ adst) {
    const int M = N_NODES;
    const int K = (MODE == 0) ? GCN_IN : F1;
    const int N = (MODE == 0) ? F1 : F2;
    const int H = (MODE == 0) ? H1 : H2;
    const __half* A  = (MODE == 0) ? (const __half*)g_xh  : (const __half*)g_o1h;
    const __half* Bt = (MODE == 0) ? (const __half*)g_w1h : (const __half*)g_w2h;
    __half* Ch = (MODE == 0) ? g_h1h : g_h2h;
    float* oas = (MODE == 0) ? g_as1 : g_as2;
    float* oad = (MODE == 0) ? g_ad1 : g_ad2;

    extern __shared__ __half smemh[];
    __half* As = smemh;                      // [STG][STAGE_H]
    __half* Bs = smemh + STG * STAGE_H;      // [STG][STAGE_H]
    __shared__ float red_s[GBM], red_d[GBM];

    int tid = threadIdx.x, lane = tid & 31, warp = tid >> 5;
    int warp_m = (warp & 3) * 32;
    int warp_n = (warp >> 2) * 64;
    int head = blockIdx.x;
    int rb = blockIdx.y * GBM, cb = head * GBN;
    int grp = lane >> 2, sub = lane & 3;

    uint32_t sAb = (uint32_t)__cvta_generic_to_shared(As);
    uint32_t sBb = (uint32_t)__cvta_generic_to_shared(Bs);
    // ldmatrix lane addresses (bytes)
    int mi = lane >> 3, r = lane & 7;
    uint32_t aoff = sAb + (((warp_m + r + 8 * (mi & 1)) * SAh + 8 * (mi >> 1)) << 1);
    uint32_t boff = sBb + (((warp_n + r + 8 * (mi >> 1)) * SAh + 8 * (mi & 1)) << 1);

    float acc[2][8][4];
    #pragma unroll
    for (int i = 0; i < 2; i++)
        #pragma unroll
        for (int j = 0; j < 8; j++)
            #pragma unroll
            for (int q = 0; q < 4; q++) acc[i][j][q] = 0.f;

    auto copy_tile = [&](int t, int buf) {
        int k0 = t * GBK;
        __half* Ab = As + buf * STAGE_H;
        __half* Bb = Bs + buf * STAGE_H;
        // 512 chunks of 16B each for A (128 rows x 4) and B; 2 each per thread
        #pragma unroll
        for (int p = 0; p < 2; p++) {
            int c = tid * 2 + p;
            int row = c >> 2, col = (c & 3) * 8;   // col in halves
            const __half* srcA = A + (size_t)(rb + row) * K + k0 + col;
            uint32_t dstA = (uint32_t)__cvta_generic_to_shared(&Ab[row * SAh + col]);
            int sz = (rb + row < M) ? 16 : 0;
            asm volatile("cp.async.cg.shared.global [%0], [%1], 16, %2;\n"
                         :: "r"(dstA), "l"(srcA), "r"(sz));
            const __half* srcB = Bt + (size_t)(cb + row) * K + k0 + col;
            uint32_t dstB = (uint32_t)__cvta_generic_to_shared(&Bb[row * SAh + col]);
            asm volatile("cp.async.cg.shared.global [%0], [%1], 16;\n"
                         :: "r"(dstB), "l"(srcB));
        }
        asm volatile("cp.async.commit_group;\n" ::: "memory");
    };

    const int T = K / GBK;
    copy_tile(0, 0);
    copy_tile(1, 1);

    for (int t = 0; t < T; t++) {
        if (t < T - 1)
            asm volatile("cp.async.wait_group 1;\n" ::: "memory");
        else
            asm volatile("cp.async.wait_group 0;\n" ::: "memory");
        __syncthreads();
        if (t + 2 < T) copy_tile(t + 2, (t + 2) % STG);

        int buf = t % STG;
        uint32_t aB = aoff + buf * (STAGE_H * 2);
        uint32_t bB = boff + buf * (STAGE_H * 2);

        #pragma unroll
        for (int ks = 0; ks < 2; ks++) {     // two k16 steps per 32-half tile
            uint32_t a0[4], a1[4];
            ldm_x4(a0, aB + ks * 32);
            ldm_x4(a1, aB + ks * 32 + 16 * SAh * 2);
            #pragma unroll
            for (int nt2 = 0; nt2 < 4; nt2++) {
                uint32_t b[4];
                ldm_x4(b, bB + ks * 32 + nt2 * (16 * SAh * 2));
                #pragma unroll
                for (int mt = 0; mt < 2; mt++) {
                    const uint32_t* a = (mt == 0) ? a0 : a1;
                    asm volatile(
                        "mma.sync.aligned.m16n8k16.row.col.f32.f16.f16.f32 "
                        "{%0,%1,%2,%3}, {%4,%5,%6,%7}, {%8,%9}, {%0,%1,%2,%3};"
                        : "+f"(acc[mt][2 * nt2][0]), "+f"(acc[mt][2 * nt2][1]),
                          "+f"(acc[mt][2 * nt2][2]), "+f"(acc[mt][2 * nt2][3])
                        : "r"(a[0]), "r"(a[1]), "r"(a[2]), "r"(a[3]),
                          "r"(b[0]), "r"(b[1]));
                    asm volatile(
                        "mma.sync.aligned.m16n8k16.row.col.f32.f16.f16.f32 "
                        "{%0,%1,%2,%3}, {%4,%5,%6,%7}, {%8,%9}, {%0,%1,%2,%3};"
                        : "+f"(acc[mt][2 * nt2 + 1][0]), "+f"(acc[mt][2 * nt2 + 1][1]),
                          "+f"(acc[mt][2 * nt2 + 1][2]), "+f"(acc[mt][2 * nt2 + 1][3])
                        : "r"(a[0]), "r"(a[1]), "r"(a[2]), "r"(a[3]),
                          "r"(b[2]), "r"(b[3]));
                }
            }
        }
    }

    // ---- store C as fp16 ----
    #pragma unroll
    for (int mt = 0; mt < 2; mt++) {
        int r0 = rb + warp_m + mt * 16 + grp;
        #pragma unroll
        for (int nt = 0; nt < 8; nt++) {
            int c0 = cb + warp_n + nt * 8 + 2 * sub;
            if (r0 < M)
                *reinterpret_cast<__half2*>(Ch + (size_t)r0 * N + c0) =
                    __floats2half2_rn(acc[mt][nt][0], acc[mt][nt][1]);
            if (r0 + 8 < M)
                *reinterpret_cast<__half2*>(Ch + (size_t)(r0 + 8) * N + c0) =
                    __floats2half2_rn(acc[mt][nt][2], acc[mt][nt][3]);
        }
    }

    // ---- fused attention dots (fp32) ----
    float ps[2][2] = {{0.f, 0.f}, {0.f, 0.f}};
    float pd[2][2] = {{0.f, 0.f}, {0.f, 0.f}};
    #pragma unroll
    for (int nt = 0; nt < 8; nt++) {
        int cc = warp_n + nt * 8 + 2 * sub;
        float s0 = asrc[head * 128 + cc],     d0 = adst[head * 128 + cc];
        float s1 = asrc[head * 128 + cc + 1], d1 = adst[head * 128 + cc + 1];
        #pragma unroll
        for (int mt = 0; mt < 2; mt++) {
            ps[mt][0] += acc[mt][nt][0] * s0 + acc[mt][nt][1] * s1;
            pd[mt][0] += acc[mt][nt][0] * d0 + acc[mt][nt][1] * d1;
            ps[mt][1] += acc[mt][nt][2] * s0 + acc[mt][nt][3] * s1;
            pd[mt][1] += acc[mt][nt][2] * d0 + acc[mt][nt][3] * d1;
        }
    }
    #pragma unroll
    for (int mt = 0; mt < 2; mt++)
        #pragma unroll
        for (int hf = 0; hf < 2; hf++) {
            #pragma unroll
            for (int o = 1; o < 4; o <<= 1) {
                ps[mt][hf] += __shfl_xor_sync(~0u, ps[mt][hf], o);
                pd[mt][hf] += __shfl_xor_sync(~0u, pd[mt][hf], o);
            }
        }
    if (warp >= 4 && sub == 0) {
        #pragma unroll
        for (int mt = 0; mt < 2; mt++)
            #pragma unroll
            for (int hf = 0; hf < 2; hf++) {
                int lr = warp_m + mt * 16 + hf * 8 + grp;
                red_s[lr] = ps[mt][hf];
                red_d[lr] = pd[mt][hf];
            }
    }
    __syncthreads();
    if (warp < 4 && sub == 0) {
        #pragma unroll
        for (int mt = 0; mt < 2; mt++)
            #pragma unroll
            for (int hf = 0; hf < 2; hf++) {
                int lr = warp_m + mt * 16 + hf * 8 + grp;
                int rr = rb + lr;
                if (rr < M) {
                    oas[rr * H + head] = ps[mt][hf] + red_s[lr];
                    oad[rr * H + head] = pd[mt][hf] + red_d[lr];
                }
            }
    }
}

// ---------------- segment softmax: store exp + 1/denom ----------------------
template<int H>
__device__ __forceinline__ void softmax_node(int n, const float* as_, const float* ad_,
                                             float* alpha, float* rinvg, int lane) {
    int beg = g_off[n], end = g_off[n + 1];
    float ad[H], m[H], dsum[H];
    #pragma unroll
    for (int h = 0; h < H; h++) { ad[h] = ad_[n * H + h]; m[h] = -1e30f; dsum[h] = 0.f; }
    for (int i = beg + lane; i < end; i += 32) {
        int s = g_src[i];
        #pragma unroll
        for (int h = 0; h < H; h++) {
            float e = leaky(as_[s * H + h] + ad[h], 0.2f);
            alpha[(size_t)i * H + h] = e;
            m[h] = fmaxf(m[h], e);
        }
    }
    #pragma unroll
    for (int h = 0; h < H; h++)
        #pragma unroll
        for (int o = 16; o; o >>= 1) m[h] = fmaxf(m[h], __shfl_xor_sync(~0u, m[h], o));
    for (int i = beg + lane; i < end; i += 32) {
        #pragma unroll
        for (int h = 0; h < H; h++) {
            float ex = expf(alpha[(size_t)i * H + h] - m[h]);
            alpha[(size_t)i * H + h] = ex;
            dsum[h] += ex;
        }
    }
    #pragma unroll
    for (int h = 0; h < H; h++)
        #pragma unroll
        for (int o = 16; o; o >>= 1) dsum[h] += __shfl_xor_sync(~0u, dsum[h], o);
    if (lane == 0)
        #pragma unroll
        for (int h = 0; h < H; h++) rinvg[n * H + h] = 1.f / (dsum[h] + 1e-16f);
}

__global__ void k_softmax1() {
    int n = (blockIdx.x * blockDim.x + threadIdx.x) >> 5;
    int lane = threadIdx.x & 31;
    if (n >= N_NODES) return;
    softmax_node<H1>(n, g_as1, g_ad1, g_alpha1, g_rinv1, lane);
}

__global__ void k_softmax2(const void* __restrict__ bbox) {
    int wi = (blockIdx.x * blockDim.x + threadIdx.x) >> 5;
    int lane = threadIdx.x & 31;
    if (wi >= N_BBOX) return;
    int n = load_idx(bbox, wi);
    int claimed = 0;
    if (lane == 0) claimed = atomicExch(&g_claim[n], 1);
    claimed = __shfl_sync(~0u, claimed, 0);
    if (claimed) return;
    softmax_node<H2>(n, g_as2, g_ad2, g_alpha2, g_rinv2, lane);
}

// ---------------- layer-1 aggregation: warp-per-head, fp16 gather -----------
__global__ void k_agg1(const float* __restrict__ b1) {
    int n = blockIdx.x;
    int head = threadIdx.x >> 5;           // 0..4
    int lane = threadIdx.x & 31;
    int c = head * 128 + lane * 4;
    int beg = g_off[n], end = g_off[n + 1];
    float4 acc = make_float4(0.f, 0.f, 0.f, 0.f);
    int i = beg;
    for (; i + 4 <= end; i += 4) {
        int s0 = g_src[i], s1 = g_src[i + 1], s2 = g_src[i + 2], s3 = g_src[i + 3];
        float a0 = g_alpha1[(size_t)(i    ) * H1 + head];
        float a1 = g_alpha1[(size_t)(i + 1) * H1 + head];
        float a2 = g_alpha1[(size_t)(i + 2) * H1 + head];
        float a3 = g_alpha1[(size_t)(i + 3) * H1 + head];
        uint2 u0 = *reinterpret_cast<const uint2*>(g_h1h + (size_t)s0 * F1 + c);
        uint2 u1 = *reinterpret_cast<const uint2*>(g_h1h + (size_t)s1 * F1 + c);
        uint2 u2 = *reinterpret_cast<const uint2*>(g_h1h + (size_t)s2 * F1 + c);
        uint2 u3 = *reinterpret_cast<const uint2*>(g_h1h + (size_t)s3 * F1 + c);
        float2 p0a = __half22float2(*reinterpret_cast<__half2*>(&u0.x));
        float2 p0b = __half22float2(*reinterpret_cast<__half2*>(&u0.y));
        float2 p1a = __half22float2(*reinterpret_cast<__half2*>(&u1.x));
        float2 p1b = __half22float2(*reinterpret_cast<__half2*>(&u1.y));
        float2 p2a = __half22float2(*reinterpret_cast<__half2*>(&u2.x));
        float2 p2b = __half22float2(*reinterpret_cast<__half2*>(&u2.y));
        float2 p3a = __half22float2(*reinterpret_cast<__half2*>(&u3.x));
        float2 p3b = __half22float2(*reinterpret_cast<__half2*>(&u3.y));
        acc.x += a0 * p0a.x + a1 * p1a.x + a2 * p2a.x + a3 * p3a.x;
        acc.y += a0 * p0a.y + a1 * p1a.y + a2 * p2a.y + a3 * p3a.y;
        acc.z += a0 * p0b.x + a1 * p1b.x + a2 * p2b.x + a3 * p3b.x;
        acc.w += a0 * p0b.y + a1 * p1b.y + a2 * p2b.y + a3 * p3b.y;
    }
    for (; i < end; i++) {
        int s = g_src[i];
        float a = g_alpha1[(size_t)i * H1 + head];
        uint2 u = *reinterpret_cast<const uint2*>(g_h1h + (size_t)s * F1 + c);
        float2 pa = __half22float2(*reinterpret_cast<__half2*>(&u.x));
        float2 pb = __half22float2(*reinterpret_cast<__half2*>(&u.y));
        acc.x += a * pa.x; acc.y += a * pa.y; acc.z += a * pb.x; acc.w += a * pb.y;
    }
    float rinv = g_rinv1[n * H1 + head];
    float4 bb = *reinterpret_cast<const float4*>(b1 + c);
    // o1 stored directly as fp16 (gemm2 A operand)
    __half2 h01 = __floats2half2_rn(leaky(acc.x * rinv + bb.x, 0.01f),
                                    leaky(acc.y * rinv + bb.y, 0.01f));
    __half2 h23 = __floats2half2_rn(leaky(acc.z * rinv + bb.z, 0.01f),
                                    leaky(acc.w * rinv + bb.w, 0.01f));
    uint2 st;
    st.x = *reinterpret_cast<uint32_t*>(&h01);
    st.y = *reinterpret_cast<uint32_t*>(&h23);
    *reinterpret_cast<uint2*>(g_o1h + (size_t)n * F1 + c) = st;
}

// ---------------- layer-2 aggregation: bbox only, fp16 gather ---------------
__global__ void k_agg2(const void* __restrict__ bbox, const float* __restrict__ b2,
                       float* __restrict__ out) {
    __shared__ float4 red[H2][32];
    int bi = blockIdx.x;
    int head = threadIdx.x >> 5;           // 0..2
    int lane = threadIdx.x & 31;
    int c = head * 128 + lane * 4;
    int n = load_idx(bbox, bi);
    int beg = g_off[n], end = g_off[n + 1];
    float4 acc = make_float4(0.f, 0.f, 0.f, 0.f);
    int e = beg;
    for (; e + 4 <= end; e += 4) {
        int s0 = g_src[e], s1 = g_src[e + 1], s2 = g_src[e + 2], s3 = g_src[e + 3];
        float a0 = g_alpha2[(size_t)(e    ) * H2 + head];
        float a1 = g_alpha2[(size_t)(e + 1) * H2 + head];
        float a2 = g_alpha2[(size_t)(e + 2) * H2 + head];
        float a3 = g_alpha2[(size_t)(e + 3) * H2 + head];
        uint2 u0 = *reinterpret_cast<const uint2*>(g_h2h + (size_t)s0 * F2 + c);
        uint2 u1 = *reinterpret_cast<const uint2*>(g_h2h + (size_t)s1 * F2 + c);
        uint2 u2 = *reinterpret_cast<const uint2*>(g_h2h + (size_t)s2 * F2 + c);
        uint2 u3 = *reinterpret_cast<const uint2*>(g_h2h + (size_t)s3 * F2 + c);
        float2 p0a = __half22float2(*reinterpret_cast<__half2*>(&u0.x));
        float2 p0b = __half22float2(*reinterpret_cast<__half2*>(&u0.y));
        float2 p1a = __half22float2(*reinterpret_cast<__half2*>(&u1.x));
        float2 p1b = __half22float2(*reinterpret_cast<__half2*>(&u1.y));
        float2 p2a = __half22float2(*reinterpret_cast<__half2*>(&u2.x));
        float2 p2b = __half22float2(*reinterpret_cast<__half2*>(&u2.y));
        float2 p3a = __half22float2(*reinterpret_cast<__half2*>(&u3.x));
        float2 p3b = __half22float2(*reinterpret_cast<__half2*>(&u3.y));
        acc.x += a0 * p0a.x + a1 * p1a.x + a2 * p2a.x + a3 * p3a.x;
        acc.y += a0 * p0a.y + a1 * p1a.y + a2 * p2a.y + a3 * p3a.y;
        acc.z += a0 * p0b.x + a1 * p1b.x + a2 * p2b.x + a3 * p3b.x;
        acc.w += a0 * p0b.y + a1 * p1b.y + a2 * p2b.y + a3 * p3b.y;
    }
    for (; e < end; e++) {
        int s = g_src[e];
        float a = g_alpha2[(size_t)e * H2 + head];
        uint2 u = *reinterpret_cast<const uint2*>(g_h2h + (size_t)s * F2 + c);
        float2 pa = __half22float2(*reinterpret_cast<__half2*>(&u.x));
        float2 pb = __half22float2(*reinterpret_cast<__half2*>(&u.y));
        acc.x += a * pa.x; acc.y += a * pa.y; acc.z += a * pb.x; acc.w += a * pb.y;
    }
    float rinv = g_rinv2[n * H2 + head];
    acc.x *= rinv; acc.y *= rinv; acc.z *= rinv; acc.w *= rinv;
    red[head][lane] = acc;
    __syncthreads();
    if (head == 0) {
        float4 r0 = red[0][lane], r1 = red[1][lane], r2 = red[2][lane];
        float4 bb = *reinterpret_cast<const float4*>(b2 + lane * 4);
        float4 o;
        o.x = leaky((r0.x + r1.x + r2.x) * (1.f / 3.f) + bb.x, 0.01f);
        o.y = leaky((r0.y + r1.y + r2.y) * (1.f / 3.f) + bb.y, 0.01f);
        o.z = leaky((r0.z + r1.z + r2.z) * (1.f / 3.f) + bb.z, 0.01f);
        o.w = leaky((r0.w + r1.w + r2.w) * (1.f / 3.f) + bb.w, 0.01f);
        *reinterpret_cast<float4*>(out + (size_t)bi * 128 + lane * 4) = o;
    }
}

// ---------------- launch ----------------------------------------------------
extern "C" void kernel_launch(void* const* d_in, const int* in_sizes, int n_in,
                              void* d_out, int out_size) {
    const float *x = nullptr, *W1 = nullptr, *W2 = nullptr, *b1 = nullptr, *b2 = nullptr;
    const float *att_src1 = nullptr, *att_dst1 = nullptr;
    const float *att_src2 = nullptr, *att_dst2 = nullptr;
    const void *ei = nullptr, *bbox = nullptr;
    int n640 = 0, n384 = 0;
    for (int i = 0; i < n_in; i++) {
        switch (in_sizes[i]) {
            case N_NODES * GCN_IN: x    = (const float*)d_in[i]; break;
            case 2 * N_EDGES:      ei   = d_in[i]; break;
            case N_BBOX:           bbox = d_in[i]; break;
            case GCN_IN * F1:      W1   = (const float*)d_in[i]; break;
            case F1 * F2:          W2   = (const float*)d_in[i]; break;
            case C2:               b2   = (const float*)d_in[i]; break;
            case F1:
                if      (n640 == 0) att_src1 = (const float*)d_in[i];
                else if (n640 == 1) att_dst1 = (const float*)d_in[i];
                else                b1       = (const float*)d_in[i];
                n640++; break;
            case F2:
                if (n384 == 0) att_src2 = (const float*)d_in[i];
                else           att_dst2 = (const float*)d_in[i];
                n384++; break;
            default: break;
        }
    }
    float* out = (float*)d_out;

    __half *xh, *w1h, *w2h;
    cudaGetSymbolAddress((void**)&xh,  g_xh);
    cudaGetSymbolAddress((void**)&w1h, g_w1h);
    cudaGetSymbolAddress((void**)&w2h, g_w2h);

    cudaFuncSetAttribute(gemm_f16<0>, cudaFuncAttributeMaxDynamicSharedMemorySize, GEMM_SMEM);
    cudaFuncSetAttribute(gemm_f16<1>, cudaFuncAttributeMaxDynamicSharedMemorySize, GEMM_SMEM);

    k_detect<<<1, 1>>>(ei);
    k_tohalf<<<(N_NODES * GCN_IN / 8 + 255) / 256, 256>>>(x, xh, N_NODES * GCN_IN / 8);
    k_transpose_h<<<dim3(F1 / 32, GCN_IN / 32), dim3(32, 8)>>>(W1, w1h, GCN_IN, F1);
    {   // profiled slot
        dim3 g(F1 / GBN, (N_NODES + GBM - 1) / GBM);
        gemm_f16<0><<<g, 256, GEMM_SMEM>>>(att_src1, att_dst1);
    }
    k_transpose_h<<<dim3(F2 / 32, F1 / 32), dim3(32, 8)>>>(W2, w2h, F1, F2);
    k_zero<<<(N_NODES + 255) / 256, 256>>>();
    k_hist<<<(ET + 255) / 256, 256>>>(ei);
    k_scan1<<<NB_SCAN, 1024>>>();
    k_scan2<<<1, 32>>>();
    k_scan3<<<NB_SCAN, 1024>>>();
    k_scatter<<<(ET + 255) / 256, 256>>>(ei);

    k_softmax1<<<(N_NODES * 32 + 255) / 256, 256>>>();
    k_agg1<<<N_NODES, H1 * 32>>>(b1);

    {
        dim3 g(F2 / GBN, (N_NODES + GBM - 1) / GBM);
        gemm_f16<1><<<g, 256, GEMM_SMEM>>>(att_src2, att_dst2);
    }
    k_softmax2<<<(N_BBOX * 32 + 255) / 256, 256>>>(bbox);
    k_agg2<<<N_BBOX, H2 * 32>>>(bbox, b2, out);
}

// round 12
// speedup vs baseline: 1.4800x; 1.0602x over previous
#include <cuda_runtime.h>
#include <cuda_fp16.h>
#include <cstdint>

#define N_NODES 20000
#define N_EDGES 320000
#define ET      (N_EDGES + N_NODES)   // 340000
#define GCN_IN  256
#define C1      128
#define H1      5
#define F1      (H1*C1)               // 640
#define C2      128
#define H2      3
#define F2      (H2*C2)               // 384
#define N_BBOX  4096
#define NB_SCAN ((N_NODES + 1023) / 1024)   // 20

// ---------------- scratch ---------------------------------------------------
__device__ int    g_is64;
__device__ int    g_cnt[N_NODES];
__device__ int    g_cur[N_NODES];
__device__ int    g_claim[N_NODES];
__device__ int    g_off[N_NODES + 1];
__device__ int    g_src[ET];
__device__ int    g_bsum[32];
__device__ int    g_bpre[32];
__device__ __half g_xh[(size_t)N_NODES * GCN_IN];   // x as fp16
__device__ __half g_w1h[F1 * GCN_IN];               // W1^T fp16 [F1][256]
__device__ __half g_w2h[F2 * F1];                   // W2^T fp16 [F2][640]
__device__ __half g_h1h[(size_t)N_NODES * F1];      // h1 fp16 (gather-only)
__device__ __half g_h2h[(size_t)N_NODES * F2];      // h2 fp16 (gather-only)
__device__ __half g_o1h[(size_t)N_NODES * F1];      // layer1 out fp16 (gemm2 A)
__device__ float  g_as1[N_NODES * H1];
__device__ float  g_ad1[N_NODES * H1];
__device__ float  g_as2[N_NODES * H2];
__device__ float  g_ad2[N_NODES * H2];
__device__ float  g_rinv1[N_NODES * H1];
__device__ float  g_rinv2[N_NODES * H2];
__device__ float  g_alpha1[(size_t)ET * H1];
__device__ float  g_alpha2[(size_t)ET * H2];

__device__ __forceinline__ float leaky(float x, float s) {
    return x >= 0.f ? x : s * x;
}
__device__ __forceinline__ int load_idx(const void* p, long long i) {
    return g_is64 ? (int)((const long long*)p)[i] : ((const int*)p)[i];
}
__device__ __forceinline__ void ldm_x4(uint32_t (&r)[4], uint32_t addr) {
    asm volatile("ldmatrix.sync.aligned.m8n8.x4.shared.b16 {%0,%1,%2,%3}, [%4];"
                 : "=r"(r[0]), "=r"(r[1]), "=r"(r[2]), "=r"(r[3]) : "r"(addr));
}

// ---------------- dtype sniff -----------------------------------------------
__global__ void k_detect(const void* ei) {
    const int* p = (const int*)ei;
    int nz = 0;
    #pragma unroll
    for (int i = 0; i < 64; i++) nz |= p[2 * i + 1];
    g_is64 = (nz == 0) ? 1 : 0;
}

// ---------------- fp32 -> fp16 convert (8 elems/thread) ---------------------
__global__ void k_tohalf(const float* __restrict__ in, __half* __restrict__ out, int n8) {
    int i = blockIdx.x * blockDim.x + threadIdx.x;
    if (i >= n8) return;
    float4 v0 = reinterpret_cast<const float4*>(in)[2 * i];
    float4 v1 = reinterpret_cast<const float4*>(in)[2 * i + 1];
    __half2 h[4];
    h[0] = __floats2half2_rn(v0.x, v0.y);
    h[1] = __floats2half2_rn(v0.z, v0.w);
    h[2] = __floats2half2_rn(v1.x, v1.y);
    h[3] = __floats2half2_rn(v1.z, v1.w);
    reinterpret_cast<uint4*>(out)[i] = *reinterpret_cast<uint4*>(h);
}

// ---------------- transpose -> fp16: W[K][N] -> Wt[N][K] --------------------
__global__ void k_transpose_h(const float* __restrict__ in, __half* __restrict__ out,
                              int K, int N) {
    __shared__ float tile[32][33];
    int n0 = blockIdx.x * 32, k0 = blockIdx.y * 32;
    int tx = threadIdx.x, ty = threadIdx.y;
    #pragma unroll
    for (int j = 0; j < 32; j += 8)
        tile[ty + j][tx] = in[(size_t)(k0 + ty + j) * N + n0 + tx];
    __syncthreads();
    #pragma unroll
    for (int j = 0; j < 32; j += 8)
        out[(size_t)(n0 + ty + j) * K + k0 + tx] = __float2half(tile[tx][ty + j]);
}

// ---------------- CSR build -------------------------------------------------
__global__ void k_zero() {
    int i = blockIdx.x * blockDim.x + threadIdx.x;
    if (i < N_NODES) { g_cnt[i] = 0; g_cur[i] = 0; g_claim[i] = 0; }
}

__global__ void k_hist(const void* __restrict__ ei) {
    int e = blockIdx.x * blockDim.x + threadIdx.x;
    if (e >= ET) return;
    int dst = (e < N_EDGES) ? load_idx(ei, (long long)N_EDGES + e) : (e - N_EDGES);
    atomicAdd(&g_cnt[dst], 1);
}

__global__ void k_scan1() {
    __shared__ int ws[32];
    int tid = threadIdx.x, lane = tid & 31, wid = tid >> 5;
    int i = blockIdx.x * 1024 + tid;
    int v = (i < N_NODES) ? g_cnt[i] : 0;
    int x = v;
    #pragma unroll
    for (int o = 1; o < 32; o <<= 1) {
        int y = __shfl_up_sync(~0u, x, o);
        if (lane >= o) x += y;
    }
    if (lane == 31) ws[wid] = x;
    __syncthreads();
    if (wid == 0) {
        int w = ws[lane];
        #pragma unroll
        for (int o = 1; o < 32; o <<= 1) {
            int y = __shfl_up_sync(~0u, w, o);
            if (lane >= o) w += y;
        }
        ws[lane] = w;
    }
    __syncthreads();
    int incl = x + (wid > 0 ? ws[wid - 1] : 0);
    if (i < N_NODES) g_off[i + 1] = incl;
    if (tid == 1023) g_bsum[blockIdx.x] = incl;
}

__global__ void k_scan2() {
    int lane = threadIdx.x;
    int v = (lane < NB_SCAN) ? g_bsum[lane] : 0;
    int x = v;
    #pragma unroll
    for (int o = 1; o < 32; o <<= 1) {
        int y = __shfl_up_sync(~0u, x, o);
        if (lane >= o) x += y;
    }
    g_bpre[lane] = x - v;
}

__global__ void k_scan3() {
    int i = blockIdx.x * 1024 + threadIdx.x;
    if (i == 0) g_off[0] = 0;
    if (i < N_NODES) g_off[i + 1] += g_bpre[blockIdx.x];
}

__global__ void k_scatter(const void* __restrict__ ei) {
    int e = blockIdx.x * blockDim.x + threadIdx.x;
    if (e >= ET) return;
    int src, dst;
    if (e < N_EDGES) {
        src = load_idx(ei, e);
        dst = load_idx(ei, (long long)N_EDGES + e);
    } else {
        src = dst = e - N_EDGES;
    }
    int p = g_off[dst] + atomicAdd(&g_cur[dst], 1);
    g_src[p] = src;
}

// ---------------- FP16 GEMM (m16n8k16) — high occupancy ---------------------
// C[M,N] = A[M,K] @ Bt[N,K]^T. GBN=128 = one head per CTA.
// BM=64 BN=128 BK=32(halves); 8 warps (2M x 4N), warp tile 32x32; 3 CTA/SM.
#define GBM 64
#define GBN 128
#define GBK 32
#define SAh 40
#define STG 3
#define A_STAGE_H (GBM * SAh)               // 2560 halves
#define B_STAGE_H (GBN * SAh)               // 5120 halves
#define GEMM_SMEM (STG * (A_STAGE_H + B_STAGE_H) * 2)   // 46080 B

template<int MODE>
__global__ void __launch_bounds__(256, 3)
gemm_f16(const float* __restrict__ asrc, const float* __restrict__ adst) {
    const int M = N_NODES;
    const int K = (MODE == 0) ? GCN_IN : F1;
    const int N = (MODE == 0) ? F1 : F2;
    const int H = (MODE == 0) ? H1 : H2;
    const __half* A  = (MODE == 0) ? (const __half*)g_xh  : (const __half*)g_o1h;
    const __half* Bt = (MODE == 0) ? (const __half*)g_w1h : (const __half*)g_w2h;
    __half* Ch = (MODE == 0) ? g_h1h : g_h2h;
    float* oas = (MODE == 0) ? g_as1 : g_as2;
    float* oad = (MODE == 0) ? g_ad1 : g_ad2;

    extern __shared__ __half smemh[];
    __half* As = smemh;                          // [STG][A_STAGE_H]
    __half* Bs = smemh + STG * A_STAGE_H;        // [STG][B_STAGE_H]
    __shared__ float red_s[4][GBM], red_d[4][GBM];

    int tid = threadIdx.x, lane = tid & 31, warp = tid >> 5;
    int warp_m = (warp & 1) * 32;          // 0 or 32
    int warp_n = (warp >> 1) * 32;         // 0,32,64,96
    int ngrp = warp >> 1;
    int head = blockIdx.x;
    int rb = blockIdx.y * GBM, cb = head * GBN;
    int grp = lane >> 2, sub = lane & 3;

    uint32_t sAb = (uint32_t)__cvta_generic_to_shared(As);
    uint32_t sBb = (uint32_t)__cvta_generic_to_shared(Bs);
    int mi = lane >> 3, r = lane & 7;
    uint32_t aoff = sAb + (((warp_m + r + 8 * (mi & 1)) * SAh + 8 * (mi >> 1)) << 1);
    uint32_t boff = sBb + (((warp_n + r + 8 * (mi >> 1)) * SAh + 8 * (mi & 1)) << 1);

    float acc[2][4][4];
    #pragma unroll
    for (int i = 0; i < 2; i++)
        #pragma unroll
        for (int j = 0; j < 4; j++)
            #pragma unroll
            for (int q = 0; q < 4; q++) acc[i][j][q] = 0.f;

    auto copy_tile = [&](int t, int buf) {
        int k0 = t * GBK;
        __half* Ab = As + buf * A_STAGE_H;
        __half* Bb = Bs + buf * B_STAGE_H;
        // A: 64 rows x 4 chunks = 256 chunks; B: 128 x 4 = 512; total 768 = 256*3
        #pragma unroll
        for (int p = 0; p < 3; p++) {
            int c = p * 256 + tid;
            if (c < 256) {
                int row = c >> 2, col = (c & 3) * 8;
                const __half* src = A + (size_t)(rb + row) * K + k0 + col;
                uint32_t dst = (uint32_t)__cvta_generic_to_shared(&Ab[row * SAh + col]);
                int sz = (rb + row < M) ? 16 : 0;
                asm volatile("cp.async.cg.shared.global [%0], [%1], 16, %2;\n"
                             :: "r"(dst), "l"(src), "r"(sz));
            } else {
                int cB = c - 256;
                int row = cB >> 2, col = (cB & 3) * 8;
                const __half* src = Bt + (size_t)(cb + row) * K + k0 + col;
                uint32_t dst = (uint32_t)__cvta_generic_to_shared(&Bb[row * SAh + col]);
                asm volatile("cp.async.cg.shared.global [%0], [%1], 16;\n"
                             :: "r"(dst), "l"(src));
            }
        }
        asm volatile("cp.async.commit_group;\n" ::: "memory");
    };

    const int T = K / GBK;
    copy_tile(0, 0);
    copy_tile(1, 1);

    for (int t = 0; t < T; t++) {
        if (t < T - 1)
            asm volatile("cp.async.wait_group 1;\n" ::: "memory");
        else
            asm volatile("cp.async.wait_group 0;\n" ::: "memory");
        __syncthreads();
        if (t + 2 < T) copy_tile(t + 2, (t + 2) % STG);

        int buf = t % STG;
        uint32_t aB = aoff + buf * (A_STAGE_H * 2);
        uint32_t bB = boff + buf * (B_STAGE_H * 2);

        #pragma unroll
        for (int ks = 0; ks < 2; ks++) {
            uint32_t a0[4], a1[4];
            ldm_x4(a0, aB + ks * 32);
            ldm_x4(a1, aB + ks * 32 + 16 * SAh * 2);
            #pragma unroll
            for (int nt2 = 0; nt2 < 2; nt2++) {
                uint32_t b[4];
                ldm_x4(b, bB + ks * 32 + nt2 * (16 * SAh * 2));
                #pragma unroll
                for (int mt = 0; mt < 2; mt++) {
                    const uint32_t* a = (mt == 0) ? a0 : a1;
                    asm volatile(
                        "mma.sync.aligned.m16n8k16.row.col.f32.f16.f16.f32 "
                        "{%0,%1,%2,%3}, {%4,%5,%6,%7}, {%8,%9}, {%0,%1,%2,%3};"
                        : "+f"(acc[mt][2 * nt2][0]), "+f"(acc[mt][2 * nt2][1]),
                          "+f"(acc[mt][2 * nt2][2]), "+f"(acc[mt][2 * nt2][3])
                        : "r"(a[0]), "r"(a[1]), "r"(a[2]), "r"(a[3]),
                          "r"(b[0]), "r"(b[1]));
                    asm volatile(
                        "mma.sync.aligned.m16n8k16.row.col.f32.f16.f16.f32 "
                        "{%0,%1,%2,%3}, {%4,%5,%6,%7}, {%8,%9}, {%0,%1,%2,%3};"
                        : "+f"(acc[mt][2 * nt2 + 1][0]), "+f"(acc[mt][2 * nt2 + 1][1]),
                          "+f"(acc[mt][2 * nt2 + 1][2]), "+f"(acc[mt][2 * nt2 + 1][3])
                        : "r"(a[0]), "r"(a[1]), "r"(a[2]), "r"(a[3]),
                          "r"(b[2]), "r"(b[3]));
                }
            }
        }
    }

    // ---- store C as fp16 ----
    #pragma unroll
    for (int mt = 0; mt < 2; mt++) {
        int r0 = rb + warp_m + mt * 16 + grp;
        #pragma unroll
        for (int nt = 0; nt < 4; nt++) {
            int c0 = cb + warp_n + nt * 8 + 2 * sub;
            if (r0 < M)
                *reinterpret_cast<__half2*>(Ch + (size_t)r0 * N + c0) =
                    __floats2half2_rn(acc[mt][nt][0], acc[mt][nt][1]);
            if (r0 + 8 < M)
                *reinterpret_cast<__half2*>(Ch + (size_t)(r0 + 8) * N + c0) =
                    __floats2half2_rn(acc[mt][nt][2], acc[mt][nt][3]);
        }
    }

    // ---- fused attention dots ----
    float ps[2][2] = {{0.f, 0.f}, {0.f, 0.f}};
    float pd[2][2] = {{0.f, 0.f}, {0.f, 0.f}};
    #pragma unroll
    for (int nt = 0; nt < 4; nt++) {
        int cc = warp_n + nt * 8 + 2 * sub;
        float s0 = asrc[head * 128 + cc],     d0 = adst[head * 128 + cc];
        float s1 = asrc[head * 128 + cc + 1], d1 = adst[head * 128 + cc + 1];
        #pragma unroll
        for (int mt = 0; mt < 2; mt++) {
            ps[mt][0] += acc[mt][nt][0] * s0 + acc[mt][nt][1] * s1;
            pd[mt][0] += acc[mt][nt][0] * d0 + acc[mt][nt][1] * d1;
            ps[mt][1] += acc[mt][nt][2] * s0 + acc[mt][nt][3] * s1;
            pd[mt][1] += acc[mt][nt][2] * d0 + acc[mt][nt][3] * d1;
        }
    }
    #pragma unroll
    for (int mt = 0; mt < 2; mt++)
        #pragma unroll
        for (int hf = 0; hf < 2; hf++) {
            #pragma unroll
            for (int o = 1; o < 4; o <<= 1) {
                ps[mt][hf] += __shfl_xor_sync(~0u, ps[mt][hf], o);
                pd[mt][hf] += __shfl_xor_sync(~0u, pd[mt][hf], o);
            }
        }
    if (sub == 0) {
        #pragma unroll
        for (int mt = 0; mt < 2; mt++)
            #pragma unroll
            for (int hf = 0; hf < 2; hf++) {
                int lr = warp_m + mt * 16 + hf * 8 + grp;
                red_s[ngrp][lr] = ps[mt][hf];
                red_d[ngrp][lr] = pd[mt][hf];
            }
    }
    __syncthreads();
    // warps 0,1 (ngrp 0) finalize their 32-row slices
    if (ngrp == 0 && sub == 0) {
        #pragma unroll
        for (int mt = 0; mt < 2; mt++)
            #pragma unroll
            for (int hf = 0; hf < 2; hf++) {
                int lr = warp_m + mt * 16 + hf * 8 + grp;
                int rr = rb + lr;
                if (rr < M) {
                    float ts = red_s[0][lr] + red_s[1][lr] + red_s[2][lr] + red_s[3][lr];
                    float td = red_d[0][lr] + red_d[1][lr] + red_d[2][lr] + red_d[3][lr];
                    oas[rr * H + head] = ts;
                    oad[rr * H + head] = td;
                }
            }
    }
}

// ---------------- segment softmax: store exp + 1/denom ----------------------
template<int H>
__device__ __forceinline__ void softmax_node(int n, const float* as_, const float* ad_,
                                             float* alpha, float* rinvg, int lane) {
    int beg = g_off[n], end = g_off[n + 1];
    float ad[H], m[H], dsum[H];
    #pragma unroll
    for (int h = 0; h < H; h++) { ad[h] = ad_[n * H + h]; m[h] = -1e30f; dsum[h] = 0.f; }
    for (int i = beg + lane; i < end; i += 32) {
        int s = g_src[i];
        #pragma unroll
        for (int h = 0; h < H; h++) {
            float e = leaky(as_[s * H + h] + ad[h], 0.2f);
            alpha[(size_t)i * H + h] = e;
            m[h] = fmaxf(m[h], e);
        }
    }
    #pragma unroll
    for (int h = 0; h < H; h++)
        #pragma unroll
        for (int o = 16; o; o >>= 1) m[h] = fmaxf(m[h], __shfl_xor_sync(~0u, m[h], o));
    for (int i = beg + lane; i < end; i += 32) {
        #pragma unroll
        for (int h = 0; h < H; h++) {
            float ex = expf(alpha[(size_t)i * H + h] - m[h]);
            alpha[(size_t)i * H + h] = ex;
            dsum[h] += ex;
        }
    }
    #pragma unroll
    for (int h = 0; h < H; h++)
        #pragma unroll
        for (int o = 16; o; o >>= 1) dsum[h] += __shfl_xor_sync(~0u, dsum[h], o);
    if (lane == 0)
        #pragma unroll
        for (int h = 0; h < H; h++) rinvg[n * H + h] = 1.f / (dsum[h] + 1e-16f);
}

__global__ void k_softmax1() {
    int n = (blockIdx.x * blockDim.x + threadIdx.x) >> 5;
    int lane = threadIdx.x & 31;
    if (n >= N_NODES) return;
    softmax_node<H1>(n, g_as1, g_ad1, g_alpha1, g_rinv1, lane);
}

__global__ void k_softmax2(const void* __restrict__ bbox) {
    int wi = (blockIdx.x * blockDim.x + threadIdx.x) >> 5;
    int lane = threadIdx.x & 31;
    if (wi >= N_BBOX) return;
    int n = load_idx(bbox, wi);
    int claimed = 0;
    if (lane == 0) claimed = atomicExch(&g_claim[n], 1);
    claimed = __shfl_sync(~0u, claimed, 0);
    if (claimed) return;
    softmax_node<H2>(n, g_as2, g_ad2, g_alpha2, g_rinv2, lane);
}

// ---------------- layer-1 aggregation: warp-per-head, fp16 gather -----------
__global__ void k_agg1(const float* __restrict__ b1) {
    int n = blockIdx.x;
    int head = threadIdx.x >> 5;           // 0..4
    int lane = threadIdx.x & 31;
    int c = head * 128 + lane * 4;
    int beg = g_off[n], end = g_off[n + 1];
    float4 acc = make_float4(0.f, 0.f, 0.f, 0.f);
    int i = beg;
    for (; i + 4 <= end; i += 4) {
        int s0 = g_src[i], s1 = g_src[i + 1], s2 = g_src[i + 2], s3 = g_src[i + 3];
        float a0 = g_alpha1[(size_t)(i    ) * H1 + head];
        float a1 = g_alpha1[(size_t)(i + 1) * H1 + head];
        float a2 = g_alpha1[(size_t)(i + 2) * H1 + head];
        float a3 = g_alpha1[(size_t)(i + 3) * H1 + head];
        uint2 u0 = *reinterpret_cast<const uint2*>(g_h1h + (size_t)s0 * F1 + c);
        uint2 u1 = *reinterpret_cast<const uint2*>(g_h1h + (size_t)s1 * F1 + c);
        uint2 u2 = *reinterpret_cast<const uint2*>(g_h1h + (size_t)s2 * F1 + c);
        uint2 u3 = *reinterpret_cast<const uint2*>(g_h1h + (size_t)s3 * F1 + c);
        float2 p0a = __half22float2(*reinterpret_cast<__half2*>(&u0.x));
        float2 p0b = __half22float2(*reinterpret_cast<__half2*>(&u0.y));
        float2 p1a = __half22float2(*reinterpret_cast<__half2*>(&u1.x));
        float2 p1b = __half22float2(*reinterpret_cast<__half2*>(&u1.y));
        float2 p2a = __half22float2(*reinterpret_cast<__half2*>(&u2.x));
        float2 p2b = __half22float2(*reinterpret_cast<__half2*>(&u2.y));
        float2 p3a = __half22float2(*reinterpret_cast<__half2*>(&u3.x));
        float2 p3b = __half22float2(*reinterpret_cast<__half2*>(&u3.y));
        acc.x += a0 * p0a.x + a1 * p1a.x + a2 * p2a.x + a3 * p3a.x;
        acc.y += a0 * p0a.y + a1 * p1a.y + a2 * p2a.y + a3 * p3a.y;
        acc.z += a0 * p0b.x + a1 * p1b.x + a2 * p2b.x + a3 * p3b.x;
        acc.w += a0 * p0b.y + a1 * p1b.y + a2 * p2b.y + a3 * p3b.y;
    }
    for (; i < end; i++) {
        int s = g_src[i];
        float a = g_alpha1[(size_t)i * H1 + head];
        uint2 u = *reinterpret_cast<const uint2*>(g_h1h + (size_t)s * F1 + c);
        float2 pa = __half22float2(*reinterpret_cast<__half2*>(&u.x));
        float2 pb = __half22float2(*reinterpret_cast<__half2*>(&u.y));
        acc.x += a * pa.x; acc.y += a * pa.y; acc.z += a * pb.x; acc.w += a * pb.y;
    }
    float rinv = g_rinv1[n * H1 + head];
    float4 bb = *reinterpret_cast<const float4*>(b1 + c);
    __half2 h01 = __floats2half2_rn(leaky(acc.x * rinv + bb.x, 0.01f),
                                    leaky(acc.y * rinv + bb.y, 0.01f));
    __half2 h23 = __floats2half2_rn(leaky(acc.z * rinv + bb.z, 0.01f),
                                    leaky(acc.w * rinv + bb.w, 0.01f));
    uint2 st;
    st.x = *reinterpret_cast<uint32_t*>(&h01);
    st.y = *reinterpret_cast<uint32_t*>(&h23);
    *reinterpret_cast<uint2*>(g_o1h + (size_t)n * F1 + c) = st;
}

// ---------------- layer-2 aggregation: bbox only, fp16 gather ---------------
__global__ void k_agg2(const void* __restrict__ bbox, const float* __restrict__ b2,
                       float* __restrict__ out) {
    __shared__ float4 red[H2][32];
    int bi = blockIdx.x;
    int head = threadIdx.x >> 5;           // 0..2
    int lane = threadIdx.x & 31;
    int c = head * 128 + lane * 4;
    int n = load_idx(bbox, bi);
    int beg = g_off[n], end = g_off[n + 1];
    float4 acc = make_float4(0.f, 0.f, 0.f, 0.f);
    int e = beg;
    for (; e + 4 <= end; e += 4) {
        int s0 = g_src[e], s1 = g_src[e + 1], s2 = g_src[e + 2], s3 = g_src[e + 3];
        float a0 = g_alpha2[(size_t)(e    ) * H2 + head];
        float a1 = g_alpha2[(size_t)(e + 1) * H2 + head];
        float a2 = g_alpha2[(size_t)(e + 2) * H2 + head];
        float a3 = g_alpha2[(size_t)(e + 3) * H2 + head];
        uint2 u0 = *reinterpret_cast<const uint2*>(g_h2h + (size_t)s0 * F2 + c);
        uint2 u1 = *reinterpret_cast<const uint2*>(g_h2h + (size_t)s1 * F2 + c);
        uint2 u2 = *reinterpret_cast<const uint2*>(g_h2h + (size_t)s2 * F2 + c);
        uint2 u3 = *reinterpret_cast<const uint2*>(g_h2h + (size_t)s3 * F2 + c);
        float2 p0a = __half22float2(*reinterpret_cast<__half2*>(&u0.x));
        float2 p0b = __half22float2(*reinterpret_cast<__half2*>(&u0.y));
        float2 p1a = __half22float2(*reinterpret_cast<__half2*>(&u1.x));
        float2 p1b = __half22float2(*reinterpret_cast<__half2*>(&u1.y));
        float2 p2a = __half22float2(*reinterpret_cast<__half2*>(&u2.x));
        float2 p2b = __half22float2(*reinterpret_cast<__half2*>(&u2.y));
        float2 p3a = __half22float2(*reinterpret_cast<__half2*>(&u3.x));
        float2 p3b = __half22float2(*reinterpret_cast<__half2*>(&u3.y));
        acc.x += a0 * p0a.x + a1 * p1a.x + a2 * p2a.x + a3 * p3a.x;
        acc.y += a0 * p0a.y + a1 * p1a.y + a2 * p2a.y + a3 * p3a.y;
        acc.z += a0 * p0b.x + a1 * p1b.x + a2 * p2b.x + a3 * p3b.x;
        acc.w += a0 * p0b.y + a1 * p1b.y + a2 * p2b.y + a3 * p3b.y;
    }
    for (; e < end; e++) {
        int s = g_src[e];
        float a = g_alpha2[(size_t)e * H2 + head];
        uint2 u = *reinterpret_cast<const uint2*>(g_h2h + (size_t)s * F2 + c);
        float2 pa = __half22float2(*reinterpret_cast<__half2*>(&u.x));
        float2 pb = __half22float2(*reinterpret_cast<__half2*>(&u.y));
        acc.x += a * pa.x; acc.y += a * pa.y; acc.z += a * pb.x; acc.w += a * pb.y;
    }
    float rinv = g_rinv2[n * H2 + head];
    acc.x *= rinv; acc.y *= rinv; acc.z *= rinv; acc.w *= rinv;
    red[head][lane] = acc;
    __syncthreads();
    if (head == 0) {
        float4 r0 = red[0][lane], r1 = red[1][lane], r2 = red[2][lane];
        float4 bb = *reinterpret_cast<const float4*>(b2 + lane * 4);
        float4 o;
        o.x = leaky((r0.x + r1.x + r2.x) * (1.f / 3.f) + bb.x, 0.01f);
        o.y = leaky((r0.y + r1.y + r2.y) * (1.f / 3.f) + bb.y, 0.01f);
        o.z = leaky((r0.z + r1.z + r2.z) * (1.f / 3.f) + bb.z, 0.01f);
        o.w = leaky((r0.w + r1.w + r2.w) * (1.f / 3.f) + bb.w, 0.01f);
        *reinterpret_cast<float4*>(out + (size_t)bi * 128 + lane * 4) = o;
    }
}

// ---------------- launch ----------------------------------------------------
extern "C" void kernel_launch(void* const* d_in, const int* in_sizes, int n_in,
                              void* d_out, int out_size) {
    const float *x = nullptr, *W1 = nullptr, *W2 = nullptr, *b1 = nullptr, *b2 = nullptr;
    const float *att_src1 = nullptr, *att_dst1 = nullptr;
    const float *att_src2 = nullptr, *att_dst2 = nullptr;
    const void *ei = nullptr, *bbox = nullptr;
    int n640 = 0, n384 = 0;
    for (int i = 0; i < n_in; i++) {
        switch (in_sizes[i]) {
            case N_NODES * GCN_IN: x    = (const float*)d_in[i]; break;
            case 2 * N_EDGES:      ei   = d_in[i]; break;
            case N_BBOX:           bbox = d_in[i]; break;
            case GCN_IN * F1:      W1   = (const float*)d_in[i]; break;
            case F1 * F2:          W2   = (const float*)d_in[i]; break;
            case C2:               b2   = (const float*)d_in[i]; break;
            case F1:
                if      (n640 == 0) att_src1 = (const float*)d_in[i];
                else if (n640 == 1) att_dst1 = (const float*)d_in[i];
                else                b1       = (const float*)d_in[i];
                n640++; break;
            case F2:
                if (n384 == 0) att_src2 = (const float*)d_in[i];
                else           att_dst2 = (const float*)d_in[i];
                n384++; break;
            default: break;
        }
    }
    float* out = (float*)d_out;

    __half *xh, *w1h, *w2h;
    cudaGetSymbolAddress((void**)&xh,  g_xh);
    cudaGetSymbolAddress((void**)&w1h, g_w1h);
    cudaGetSymbolAddress((void**)&w2h, g_w2h);

    cudaFuncSetAttribute(gemm_f16<0>, cudaFuncAttributeMaxDynamicSharedMemorySize, GEMM_SMEM);
    cudaFuncSetAttribute(gemm_f16<1>, cudaFuncAttributeMaxDynamicSharedMemorySize, GEMM_SMEM);

    k_detect<<<1, 1>>>(ei);
    k_tohalf<<<(N_NODES * GCN_IN / 8 + 255) / 256, 256>>>(x, xh, N_NODES * GCN_IN / 8);
    k_transpose_h<<<dim3(F1 / 32, GCN_IN / 32), dim3(32, 8)>>>(W1, w1h, GCN_IN, F1);
    {   // profiled slot
        dim3 g(F1 / GBN, (N_NODES + GBM - 1) / GBM);
        gemm_f16<0><<<g, 256, GEMM_SMEM>>>(att_src1, att_dst1);
    }
    k_transpose_h<<<dim3(F2 / 32, F1 / 32), dim3(32, 8)>>>(W2, w2h, F1, F2);
    k_zero<<<(N_NODES + 255) / 256, 256>>>();
    k_hist<<<(ET + 255) / 256, 256>>>(ei);
    k_scan1<<<NB_SCAN, 1024>>>();
    k_scan2<<<1, 32>>>();
    k_scan3<<<NB_SCAN, 1024>>>();
    k_scatter<<<(ET + 255) / 256, 256>>>(ei);

    k_softmax1<<<(N_NODES * 32 + 255) / 256, 256>>>();
    k_agg1<<<N_NODES, H1 * 32>>>(b1);

    {
        dim3 g(F2 / GBN, (N_NODES + GBM - 1) / GBM);
        gemm_f16<1><<<g, 256, GEMM_SMEM>>>(att_src2, att_dst2);
    }
    k_softmax2<<<(N_BBOX * 32 + 255) / 256, 256>>>(bbox);
    k_agg2<<<N_BBOX, H2 * 32>>>(bbox, b2, out);
}

// round 13
// speedup vs baseline: 1.5914x; 1.0753x over previous
#include <cuda_runtime.h>
#include <cuda_fp16.h>
#include <cstdint>

#define N_NODES 20000
#define N_EDGES 320000
#define ET      (N_EDGES + N_NODES)   // 340000
#define GCN_IN  256
#define C1      128
#define H1      5
#define F1      (H1*C1)               // 640
#define C2      128
#define H2      3
#define F2      (H2*C2)               // 384
#define N_BBOX  4096
#define NB_SCAN ((N_NODES + 1023) / 1024)   // 20
#define MAXDEG  256                   // degree cap for smem softmax (Poisson(16)+1)

// ---------------- scratch ---------------------------------------------------
__device__ int    g_is64;
__device__ int    g_cnt[N_NODES];
__device__ int    g_cur[N_NODES];
__device__ int    g_off[N_NODES + 1];
__device__ int    g_src[ET];
__device__ int    g_bsum[32];
__device__ int    g_bpre[32];
__device__ __half g_xh[(size_t)N_NODES * GCN_IN];   // x as fp16
__device__ __half g_w1h[F1 * GCN_IN];               // W1^T fp16 [F1][256]
__device__ __half g_w2h[F2 * F1];                   // W2^T fp16 [F2][640]
__device__ __half g_h1h[(size_t)N_NODES * F1];      // h1 fp16 (gather-only)
__device__ __half g_h2h[(size_t)N_NODES * F2];      // h2 fp16 (gather-only)
__device__ __half g_o1h[(size_t)N_NODES * F1];      // layer1 out fp16 (gemm2 A)
__device__ float  g_as1[N_NODES * H1];
__device__ float  g_ad1[N_NODES * H1];
__device__ float  g_as2[N_NODES * H2];
__device__ float  g_ad2[N_NODES * H2];

__device__ __forceinline__ float leaky(float x, float s) {
    return x >= 0.f ? x : s * x;
}
__device__ __forceinline__ int load_idx(const void* p, long long i) {
    return g_is64 ? (int)((const long long*)p)[i] : ((const int*)p)[i];
}
__device__ __forceinline__ void ldm_x4(uint32_t (&r)[4], uint32_t addr) {
    asm volatile("ldmatrix.sync.aligned.m8n8.x4.shared.b16 {%0,%1,%2,%3}, [%4];"
                 : "=r"(r[0]), "=r"(r[1]), "=r"(r[2]), "=r"(r[3]) : "r"(addr));
}

// ---------------- prep: dtype sniff + counter zero --------------------------
__global__ void k_prep(const void* ei) {
    int i = blockIdx.x * blockDim.x + threadIdx.x;
    if (i == 0) {
        const int* p = (const int*)ei;
        int nz = 0;
        #pragma unroll
        for (int j = 0; j < 64; j++) nz |= p[2 * j + 1];
        g_is64 = (nz == 0) ? 1 : 0;
    }
    if (i < N_NODES) { g_cnt[i] = 0; g_cur[i] = 0; }
}

// ---------------- fp32 -> fp16 convert (8 elems/thread) ---------------------
__global__ void k_tohalf(const float* __restrict__ in, __half* __restrict__ out, int n8) {
    int i = blockIdx.x * blockDim.x + threadIdx.x;
    if (i >= n8) return;
    float4 v0 = reinterpret_cast<const float4*>(in)[2 * i];
    float4 v1 = reinterpret_cast<const float4*>(in)[2 * i + 1];
    __half2 h[4];
    h[0] = __floats2half2_rn(v0.x, v0.y);
    h[1] = __floats2half2_rn(v0.z, v0.w);
    h[2] = __floats2half2_rn(v1.x, v1.y);
    h[3] = __floats2half2_rn(v1.z, v1.w);
    reinterpret_cast<uint4*>(out)[i] = *reinterpret_cast<uint4*>(h);
}

// ---------------- transpose -> fp16: W[K][N] -> Wt[N][K] --------------------
__global__ void k_transpose_h(const float* __restrict__ in, __half* __restrict__ out,
                              int K, int N) {
    __shared__ float tile[32][33];
    int n0 = blockIdx.x * 32, k0 = blockIdx.y * 32;
    int tx = threadIdx.x, ty = threadIdx.y;
    #pragma unroll
    for (int j = 0; j < 32; j += 8)
        tile[ty + j][tx] = in[(size_t)(k0 + ty + j) * N + n0 + tx];
    __syncthreads();
    #pragma unroll
    for (int j = 0; j < 32; j += 8)
        out[(size_t)(n0 + ty + j) * K + k0 + tx] = __float2half(tile[tx][ty + j]);
}

// ---------------- CSR build -------------------------------------------------
__global__ void k_hist(const void* __restrict__ ei) {
    int e = blockIdx.x * blockDim.x + threadIdx.x;
    if (e >= ET) return;
    int dst = (e < N_EDGES) ? load_idx(ei, (long long)N_EDGES + e) : (e - N_EDGES);
    atomicAdd(&g_cnt[dst], 1);
}

__global__ void k_scan1() {
    __shared__ int ws[32];
    int tid = threadIdx.x, lane = tid & 31, wid = tid >> 5;
    int i = blockIdx.x * 1024 + tid;
    int v = (i < N_NODES) ? g_cnt[i] : 0;
    int x = v;
    #pragma unroll
    for (int o = 1; o < 32; o <<= 1) {
        int y = __shfl_up_sync(~0u, x, o);
        if (lane >= o) x += y;
    }
    if (lane == 31) ws[wid] = x;
    __syncthreads();
    if (wid == 0) {
        int w = ws[lane];
        #pragma unroll
        for (int o = 1; o < 32; o <<= 1) {
            int y = __shfl_up_sync(~0u, w, o);
            if (lane >= o) w += y;
        }
        ws[lane] = w;
    }
    __syncthreads();
    int incl = x + (wid > 0 ? ws[wid - 1] : 0);
    if (i < N_NODES) g_off[i + 1] = incl;
    if (tid == 1023) g_bsum[blockIdx.x] = incl;
}

__global__ void k_scan2() {
    int lane = threadIdx.x;
    int v = (lane < NB_SCAN) ? g_bsum[lane] : 0;
    int x = v;
    #pragma unroll
    for (int o = 1; o < 32; o <<= 1) {
        int y = __shfl_up_sync(~0u, x, o);
        if (lane >= o) x += y;
    }
    g_bpre[lane] = x - v;
}

__global__ void k_scan3() {
    int i = blockIdx.x * 1024 + threadIdx.x;
    if (i == 0) g_off[0] = 0;
    if (i < N_NODES) g_off[i + 1] += g_bpre[blockIdx.x];
}

__global__ void k_scatter(const void* __restrict__ ei) {
    int e = blockIdx.x * blockDim.x + threadIdx.x;
    if (e >= ET) return;
    int src, dst;
    if (e < N_EDGES) {
        src = load_idx(ei, e);
        dst = load_idx(ei, (long long)N_EDGES + e);
    } else {
        src = dst = e - N_EDGES;
    }
    int p = g_off[dst] + atomicAdd(&g_cur[dst], 1);
    g_src[p] = src;
}

// ---------------- FP16 GEMM (m16n8k16) — high occupancy ---------------------
// C[M,N] = A[M,K] @ Bt[N,K]^T. GBN=128 = one head per CTA.
// BM=64 BN=128 BK=32(halves); 8 warps (2M x 4N), warp tile 32x32; 3 CTA/SM.
#define GBM 64
#define GBN 128
#define GBK 32
#define SAh 40
#define STG 3
#define A_STAGE_H (GBM * SAh)               // 2560 halves
#define B_STAGE_H (GBN * SAh)               // 5120 halves
#define GEMM_SMEM (STG * (A_STAGE_H + B_STAGE_H) * 2)   // 46080 B

template<int MODE>
__global__ void __launch_bounds__(256, 3)
gemm_f16(const float* __restrict__ asrc, const float* __restrict__ adst) {
    const int M = N_NODES;
    const int K = (MODE == 0) ? GCN_IN : F1;
    const int N = (MODE == 0) ? F1 : F2;
    const int H = (MODE == 0) ? H1 : H2;
    const __half* A  = (MODE == 0) ? (const __half*)g_xh  : (const __half*)g_o1h;
    const __half* Bt = (MODE == 0) ? (const __half*)g_w1h : (const __half*)g_w2h;
    __half* Ch = (MODE == 0) ? g_h1h : g_h2h;
    float* oas = (MODE == 0) ? g_as1 : g_as2;
    float* oad = (MODE == 0) ? g_ad1 : g_ad2;

    extern __shared__ __half smemh[];
    __half* As = smemh;                          // [STG][A_STAGE_H]
    __half* Bs = smemh + STG * A_STAGE_H;        // [STG][B_STAGE_H]
    __shared__ float red_s[4][GBM], red_d[4][GBM];

    int tid = threadIdx.x, lane = tid & 31, warp = tid >> 5;
    int warp_m = (warp & 1) * 32;          // 0 or 32
    int warp_n = (warp >> 1) * 32;         // 0,32,64,96
    int ngrp = warp >> 1;
    int head = blockIdx.x;
    int rb = blockIdx.y * GBM, cb = head * GBN;
    int grp = lane >> 2, sub = lane & 3;

    uint32_t sAb = (uint32_t)__cvta_generic_to_shared(As);
    uint32_t sBb = (uint32_t)__cvta_generic_to_shared(Bs);
    int mi = lane >> 3, r = lane & 7;
    uint32_t aoff = sAb + (((warp_m + r + 8 * (mi & 1)) * SAh + 8 * (mi >> 1)) << 1);
    uint32_t boff = sBb + (((warp_n + r + 8 * (mi >> 1)) * SAh + 8 * (mi & 1)) << 1);

    float acc[2][4][4];
    #pragma unroll
    for (int i = 0; i < 2; i++)
        #pragma unroll
        for (int j = 0; j < 4; j++)
            #pragma unroll
            for (int q = 0; q < 4; q++) acc[i][j][q] = 0.f;

    auto copy_tile = [&](int t, int buf) {
        int k0 = t * GBK;
        __half* Ab = As + buf * A_STAGE_H;
        __half* Bb = Bs + buf * B_STAGE_H;
        #pragma unroll
        for (int p = 0; p < 3; p++) {
            int c = p * 256 + tid;
            if (c < 256) {
                int row = c >> 2, col = (c & 3) * 8;
                const __half* src = A + (size_t)(rb + row) * K + k0 + col;
                uint32_t dst = (uint32_t)__cvta_generic_to_shared(&Ab[row * SAh + col]);
                int sz = (rb + row < M) ? 16 : 0;
                asm volatile("cp.async.cg.shared.global [%0], [%1], 16, %2;\n"
                             :: "r"(dst), "l"(src), "r"(sz));
            } else {
                int cB = c - 256;
                int row = cB >> 2, col = (cB & 3) * 8;
                const __half* src = Bt + (size_t)(cb + row) * K + k0 + col;
                uint32_t dst = (uint32_t)__cvta_generic_to_shared(&Bb[row * SAh + col]);
                asm volatile("cp.async.cg.shared.global [%0], [%1], 16;\n"
                             :: "r"(dst), "l"(src));
            }
        }
        asm volatile("cp.async.commit_group;\n" ::: "memory");
    };

    const int T = K / GBK;
    copy_tile(0, 0);
    copy_tile(1, 1);

    for (int t = 0; t < T; t++) {
        if (t < T - 1)
            asm volatile("cp.async.wait_group 1;\n" ::: "memory");
        else
            asm volatile("cp.async.wait_group 0;\n" ::: "memory");
        __syncthreads();
        if (t + 2 < T) copy_tile(t + 2, (t + 2) % STG);

        int buf = t % STG;
        uint32_t aB = aoff + buf * (A_STAGE_H * 2);
        uint32_t bB = boff + buf * (B_STAGE_H * 2);

        #pragma unroll
        for (int ks = 0; ks < 2; ks++) {
            uint32_t a0[4], a1[4];
            ldm_x4(a0, aB + ks * 32);
            ldm_x4(a1, aB + ks * 32 + 16 * SAh * 2);
            #pragma unroll
            for (int nt2 = 0; nt2 < 2; nt2++) {
                uint32_t b[4];
                ldm_x4(b, bB + ks * 32 + nt2 * (16 * SAh * 2));
                #pragma unroll
                for (int mt = 0; mt < 2; mt++) {
                    const uint32_t* a = (mt == 0) ? a0 : a1;
                    asm volatile(
                        "mma.sync.aligned.m16n8k16.row.col.f32.f16.f16.f32 "
                        "{%0,%1,%2,%3}, {%4,%5,%6,%7}, {%8,%9}, {%0,%1,%2,%3};"
                        : "+f"(acc[mt][2 * nt2][0]), "+f"(acc[mt][2 * nt2][1]),
                          "+f"(acc[mt][2 * nt2][2]), "+f"(acc[mt][2 * nt2][3])
                        : "r"(a[0]), "r"(a[1]), "r"(a[2]), "r"(a[3]),
                          "r"(b[0]), "r"(b[1]));
                    asm volatile(
                        "mma.sync.aligned.m16n8k16.row.col.f32.f16.f16.f32 "
                        "{%0,%1,%2,%3}, {%4,%5,%6,%7}, {%8,%9}, {%0,%1,%2,%3};"
                        : "+f"(acc[mt][2 * nt2 + 1][0]), "+f"(acc[mt][2 * nt2 + 1][1]),
                          "+f"(acc[mt][2 * nt2 + 1][2]), "+f"(acc[mt][2 * nt2 + 1][3])
                        : "r"(a[0]), "r"(a[1]), "r"(a[2]), "r"(a[3]),
                          "r"(b[2]), "r"(b[3]));
                }
            }
        }
    }

    // ---- store C as fp16 ----
    #pragma unroll
    for (int mt = 0; mt < 2; mt++) {
        int r0 = rb + warp_m + mt * 16 + grp;
        #pragma unroll
        for (int nt = 0; nt < 4; nt++) {
            int c0 = cb + warp_n + nt * 8 + 2 * sub;
            if (r0 < M)
                *reinterpret_cast<__half2*>(Ch + (size_t)r0 * N + c0) =
                    __floats2half2_rn(acc[mt][nt][0], acc[mt][nt][1]);
            if (r0 + 8 < M)
                *reinterpret_cast<__half2*>(Ch + (size_t)(r0 + 8) * N + c0) =
                    __floats2half2_rn(acc[mt][nt][2], acc[mt][nt][3]);
        }
    }

    // ---- fused attention dots ----
    float ps[2][2] = {{0.f, 0.f}, {0.f, 0.f}};
    float pd[2][2] = {{0.f, 0.f}, {0.f, 0.f}};
    #pragma unroll
    for (int nt = 0; nt < 4; nt++) {
        int cc = warp_n + nt * 8 + 2 * sub;
        float s0 = asrc[head * 128 + cc],     d0 = adst[head * 128 + cc];
        float s1 = asrc[head * 128 + cc + 1], d1 = adst[head * 128 + cc + 1];
        #pragma unroll
        for (int mt = 0; mt < 2; mt++) {
            ps[mt][0] += acc[mt][nt][0] * s0 + acc[mt][nt][1] * s1;
            pd[mt][0] += acc[mt][nt][0] * d0 + acc[mt][nt][1] * d1;
            ps[mt][1] += acc[mt][nt][2] * s0 + acc[mt][nt][3] * s1;
            pd[mt][1] += acc[mt][nt][2] * d0 + acc[mt][nt][3] * d1;
        }
    }
    #pragma unroll
    for (int mt = 0; mt < 2; mt++)
        #pragma unroll
        for (int hf = 0; hf < 2; hf++) {
            #pragma unroll
            for (int o = 1; o < 4; o <<= 1) {
                ps[mt][hf] += __shfl_xor_sync(~0u, ps[mt][hf], o);
                pd[mt][hf] += __shfl_xor_sync(~0u, pd[mt][hf], o);
            }
        }
    if (sub == 0) {
        #pragma unroll
        for (int mt = 0; mt < 2; mt++)
            #pragma unroll
            for (int hf = 0; hf < 2; hf++) {
                int lr = warp_m + mt * 16 + hf * 8 + grp;
                red_s[ngrp][lr] = ps[mt][hf];
                red_d[ngrp][lr] = pd[mt][hf];
            }
    }
    __syncthreads();
    if (ngrp == 0 && sub == 0) {
        #pragma unroll
        for (int mt = 0; mt < 2; mt++)
            #pragma unroll
            for (int hf = 0; hf < 2; hf++) {
                int lr = warp_m + mt * 16 + hf * 8 + grp;
                int rr = rb + lr;
                if (rr < M) {
                    float ts = red_s[0][lr] + red_s[1][lr] + red_s[2][lr] + red_s[3][lr];
                    float td = red_d[0][lr] + red_d[1][lr] + red_d[2][lr] + red_d[3][lr];
                    oas[rr * H + head] = ts;
                    oad[rr * H + head] = td;
                }
            }
    }
}

// ---------------- fused softmax + layer-1 aggregation -----------------------
// Block per node, warp per head. Softmax in smem; no global alpha.
__global__ void k_agg1(const float* __restrict__ b1) {
    __shared__ float s_alpha[MAXDEG][H1];
    int n = blockIdx.x;
    int head = threadIdx.x >> 5;           // 0..4
    int lane = threadIdx.x & 31;
    int c = head * 128 + lane * 4;
    int beg = g_off[n], end = g_off[n + 1];
    int deg = end - beg;
    float adv = g_ad1[n * H1 + head];

    // pass A: logits -> smem, max
    float m = -1e30f;
    for (int i = beg + lane; i < end; i += 32) {
        int s = g_src[i];
        float e = leaky(g_as1[s * H1 + head] + adv, 0.2f);
        int idx = i - beg;
        if (idx < MAXDEG) s_alpha[idx][head] = e;
        m = fmaxf(m, e);
    }
    #pragma unroll
    for (int o = 16; o; o >>= 1) m = fmaxf(m, __shfl_xor_sync(~0u, m, o));
    __syncwarp();

    // pass B: exp + sum
    float sum = 0.f;
    for (int idx = lane; idx < deg; idx += 32) {
        float ex;
        if (idx < MAXDEG) {
            ex = expf(s_alpha[idx][head] - m);
            s_alpha[idx][head] = ex;
        } else {
            int s = g_src[beg + idx];
            ex = expf(leaky(g_as1[s * H1 + head] + adv, 0.2f) - m);
        }
        sum += ex;
    }
    #pragma unroll
    for (int o = 16; o; o >>= 1) sum += __shfl_xor_sync(~0u, sum, o);
    float rinv = 1.f / (sum + 1e-16f);
    __syncwarp();

    // pass C: aggregate (alpha broadcast from smem)
    float4 acc = make_float4(0.f, 0.f, 0.f, 0.f);
    int i = beg;
    for (; i + 4 <= end && (i - beg) + 4 <= MAXDEG; i += 4) {
        int idx = i - beg;
        int s0 = g_src[i], s1 = g_src[i + 1], s2 = g_src[i + 2], s3 = g_src[i + 3];
        float a0 = s_alpha[idx][head];
        float a1 = s_alpha[idx + 1][head];
        float a2 = s_alpha[idx + 2][head];
        float a3 = s_alpha[idx + 3][head];
        uint2 u0 = *reinterpret_cast<const uint2*>(g_h1h + (size_t)s0 * F1 + c);
        uint2 u1 = *reinterpret_cast<const uint2*>(g_h1h + (size_t)s1 * F1 + c);
        uint2 u2 = *reinterpret_cast<const uint2*>(g_h1h + (size_t)s2 * F1 + c);
        uint2 u3 = *reinterpret_cast<const uint2*>(g_h1h + (size_t)s3 * F1 + c);
        float2 p0a = __half22float2(*reinterpret_cast<__half2*>(&u0.x));
        float2 p0b = __half22float2(*reinterpret_cast<__half2*>(&u0.y));
        float2 p1a = __half22float2(*reinterpret_cast<__half2*>(&u1.x));
        float2 p1b = __half22float2(*reinterpret_cast<__half2*>(&u1.y));
        float2 p2a = __half22float2(*reinterpret_cast<__half2*>(&u2.x));
        float2 p2b = __half22float2(*reinterpret_cast<__half2*>(&u2.y));
        float2 p3a = __half22float2(*reinterpret_cast<__half2*>(&u3.x));
        float2 p3b = __half22float2(*reinterpret_cast<__half2*>(&u3.y));
        acc.x += a0 * p0a.x + a1 * p1a.x + a2 * p2a.x + a3 * p3a.x;
        acc.y += a0 * p0a.y + a1 * p1a.y + a2 * p2a.y + a3 * p3a.y;
        acc.z += a0 * p0b.x + a1 * p1b.x + a2 * p2b.x + a3 * p3b.x;
        acc.w += a0 * p0b.y + a1 * p1b.y + a2 * p2b.y + a3 * p3b.y;
    }
    for (; i < end; i++) {
        int idx = i - beg;
        int s = g_src[i];
        float a;
        if (idx < MAXDEG) a = s_alpha[idx][head];
        else a = expf(leaky(g_as1[s * H1 + head] + adv, 0.2f) - m);
        uint2 u = *reinterpret_cast<const uint2*>(g_h1h + (size_t)s * F1 + c);
        float2 pa = __half22float2(*reinterpret_cast<__half2*>(&u.x));
        float2 pb = __half22float2(*reinterpret_cast<__half2*>(&u.y));
        acc.x += a * pa.x; acc.y += a * pa.y; acc.z += a * pb.x; acc.w += a * pb.y;
    }
    float4 bb = *reinterpret_cast<const float4*>(b1 + c);
    __half2 h01 = __floats2half2_rn(leaky(acc.x * rinv + bb.x, 0.01f),
                                    leaky(acc.y * rinv + bb.y, 0.01f));
    __half2 h23 = __floats2half2_rn(leaky(acc.z * rinv + bb.z, 0.01f),
                                    leaky(acc.w * rinv + bb.w, 0.01f));
    uint2 st;
    st.x = *reinterpret_cast<uint32_t*>(&h01);
    st.y = *reinterpret_cast<uint32_t*>(&h23);
    *reinterpret_cast<uint2*>(g_o1h + (size_t)n * F1 + c) = st;
}

// ---------------- fused softmax + layer-2 aggregation (bbox only) -----------
__global__ void k_agg2(const void* __restrict__ bbox, const float* __restrict__ b2,
                       float* __restrict__ out) {
    __shared__ float s_alpha[MAXDEG][H2];
    __shared__ float4 red[H2][32];
    int bi = blockIdx.x;
    int head = threadIdx.x >> 5;           // 0..2
    int lane = threadIdx.x & 31;
    int c = head * 128 + lane * 4;
    int n = load_idx(bbox, bi);
    int beg = g_off[n], end = g_off[n + 1];
    int deg = end - beg;
    float adv = g_ad2[n * H2 + head];

    float m = -1e30f;
    for (int i = beg + lane; i < end; i += 32) {
        int s = g_src[i];
        float e = leaky(g_as2[s * H2 + head] + adv, 0.2f);
        int idx = i - beg;
        if (idx < MAXDEG) s_alpha[idx][head] = e;
        m = fmaxf(m, e);
    }
    #pragma unroll
    for (int o = 16; o; o >>= 1) m = fmaxf(m, __shfl_xor_sync(~0u, m, o));
    __syncwarp();

    float sum = 0.f;
    for (int idx = lane; idx < deg; idx += 32) {
        float ex;
        if (idx < MAXDEG) {
            ex = expf(s_alpha[idx][head] - m);
            s_alpha[idx][head] = ex;
        } else {
            int s = g_src[beg + idx];
            ex = expf(leaky(g_as2[s * H2 + head] + adv, 0.2f) - m);
        }
        sum += ex;
    }
    #pragma unroll
    for (int o = 16; o; o >>= 1) sum += __shfl_xor_sync(~0u, sum, o);
    float rinv = 1.f / (sum + 1e-16f);
    __syncwarp();

    float4 acc = make_float4(0.f, 0.f, 0.f, 0.f);
    int e = beg;
    for (; e + 4 <= end && (e - beg) + 4 <= MAXDEG; e += 4) {
        int idx = e - beg;
        int s0 = g_src[e], s1 = g_src[e + 1], s2 = g_src[e + 2], s3 = g_src[e + 3];
        float a0 = s_alpha[idx][head];
        float a1 = s_alpha[idx + 1][head];
        float a2 = s_alpha[idx + 2][head];
        float a3 = s_alpha[idx + 3][head];
        uint2 u0 = *reinterpret_cast<const uint2*>(g_h2h + (size_t)s0 * F2 + c);
        uint2 u1 = *reinterpret_cast<const uint2*>(g_h2h + (size_t)s1 * F2 + c);
        uint2 u2 = *reinterpret_cast<const uint2*>(g_h2h + (size_t)s2 * F2 + c);
        uint2 u3 = *reinterpret_cast<const uint2*>(g_h2h + (size_t)s3 * F2 + c);
        float2 p0a = __half22float2(*reinterpret_cast<__half2*>(&u0.x));
        float2 p0b = __half22float2(*reinterpret_cast<__half2*>(&u0.y));
        float2 p1a = __half22float2(*reinterpret_cast<__half2*>(&u1.x));
        float2 p1b = __half22float2(*reinterpret_cast<__half2*>(&u1.y));
        float2 p2a = __half22float2(*reinterpret_cast<__half2*>(&u2.x));
        float2 p2b = __half22float2(*reinterpret_cast<__half2*>(&u2.y));
        float2 p3a = __half22float2(*reinterpret_cast<__half2*>(&u3.x));
        float2 p3b = __half22float2(*reinterpret_cast<__half2*>(&u3.y));
        acc.x += a0 * p0a.x + a1 * p1a.x + a2 * p2a.x + a3 * p3a.x;
        acc.y += a0 * p0a.y + a1 * p1a.y + a2 * p2a.y + a3 * p3a.y;
        acc.z += a0 * p0b.x + a1 * p1b.x + a2 * p2b.x + a3 * p3b.x;
        acc.w += a0 * p0b.y + a1 * p1b.y + a2 * p2b.y + a3 * p3b.y;
    }
    for (; e < end; e++) {
        int idx = e - beg;
        int s = g_src[e];
        float a;
        if (idx < MAXDEG) a = s_alpha[idx][head];
        else a = expf(leaky(g_as2[s * H2 + head] + adv, 0.2f) - m);
        uint2 u = *reinterpret_cast<const uint2*>(g_h2h + (size_t)s * F2 + c);
        float2 pa = __half22float2(*reinterpret_cast<__half2*>(&u.x));
        float2 pb = __half22float2(*reinterpret_cast<__half2*>(&u.y));
        acc.x += a * pa.x; acc.y += a * pa.y; acc.z += a * pb.x; acc.w += a * pb.y;
    }
    acc.x *= rinv; acc.y *= rinv; acc.z *= rinv; acc.w *= rinv;
    red[head][lane] = acc;
    __syncthreads();
    if (head == 0) {
        float4 r0 = red[0][lane], r1 = red[1][lane], r2 = red[2][lane];
        float4 bb = *reinterpret_cast<const float4*>(b2 + lane * 4);
        float4 o;
        o.x = leaky((r0.x + r1.x + r2.x) * (1.f / 3.f) + bb.x, 0.01f);
        o.y = leaky((r0.y + r1.y + r2.y) * (1.f / 3.f) + bb.y, 0.01f);
        o.z = leaky((r0.z + r1.z + r2.z) * (1.f / 3.f) + bb.z, 0.01f);
        o.w = leaky((r0.w + r1.w + r2.w) * (1.f / 3.f) + bb.w, 0.01f);
        *reinterpret_cast<float4*>(out + (size_t)bi * 128 + lane * 4) = o;
    }
}

// ---------------- launch ----------------------------------------------------
extern "C" void kernel_launch(void* const* d_in, const int* in_sizes, int n_in,
                              void* d_out, int out_size) {
    const float *x = nullptr, *W1 = nullptr, *W2 = nullptr, *b1 = nullptr, *b2 = nullptr;
    const float *att_src1 = nullptr, *att_dst1 = nullptr;
    const float *att_src2 = nullptr, *att_dst2 = nullptr;
    const void *ei = nullptr, *bbox = nullptr;
    int n640 = 0, n384 = 0;
    for (int i = 0; i < n_in; i++) {
        switch (in_sizes[i]) {
            case N_NODES * GCN_IN: x    = (const float*)d_in[i]; break;
            case 2 * N_EDGES:      ei   = d_in[i]; break;
            case N_BBOX:           bbox = d_in[i]; break;
            case GCN_IN * F1:      W1   = (const float*)d_in[i]; break;
            case F1 * F2:          W2   = (const float*)d_in[i]; break;
            case C2:               b2   = (const float*)d_in[i]; break;
            case F1:
                if      (n640 == 0) att_src1 = (const float*)d_in[i];
                else if (n640 == 1) att_dst1 = (const float*)d_in[i];
                else                b1       = (const float*)d_in[i];
                n640++; break;
            case F2:
                if (n384 == 0) att_src2 = (const float*)d_in[i];
                else           att_dst2 = (const float*)d_in[i];
                n384++; break;
            default: break;
        }
    }
    float* out = (float*)d_out;

    __half *xh, *w1h, *w2h;
    cudaGetSymbolAddress((void**)&xh,  g_xh);
    cudaGetSymbolAddress((void**)&w1h, g_w1h);
    cudaGetSymbolAddress((void**)&w2h, g_w2h);

    cudaFuncSetAttribute(gemm_f16<0>, cudaFuncAttributeMaxDynamicSharedMemorySize, GEMM_SMEM);
    cudaFuncSetAttribute(gemm_f16<1>, cudaFuncAttributeMaxDynamicSharedMemorySize, GEMM_SMEM);

    k_prep<<<(N_NODES + 255) / 256, 256>>>(ei);                              // 0
    k_tohalf<<<(N_NODES * GCN_IN / 8 + 255) / 256, 256>>>(x, xh, N_NODES * GCN_IN / 8);
    k_transpose_h<<<dim3(F1 / 32, GCN_IN / 32), dim3(32, 8)>>>(W1, w1h, GCN_IN, F1);
    {   // profiled slot
        dim3 g(F1 / GBN, (N_NODES + GBM - 1) / GBM);
        gemm_f16<0><<<g, 256, GEMM_SMEM>>>(att_src1, att_dst1);
    }
    k_transpose_h<<<dim3(F2 / 32, F1 / 32), dim3(32, 8)>>>(W2, w2h, F1, F2);
    k_hist<<<(ET + 255) / 256, 256>>>(ei);
    k_scan1<<<NB_SCAN, 1024>>>();
    k_scan2<<<1, 32>>>();
    k_scan3<<<NB_SCAN, 1024>>>();
    k_scatter<<<(ET + 255) / 256, 256>>>(ei);

    k_agg1<<<N_NODES, H1 * 32>>>(b1);

    {
        dim3 g(F2 / GBN, (N_NODES + GBM - 1) / GBM);
        gemm_f16<1><<<g, 256, GEMM_SMEM>>>(att_src2, att_dst2);
    }
    k_agg2<<<N_BBOX, H2 * 32>>>(bbox, b2, out);
}

// round 14
// speedup vs baseline: 1.6487x; 1.0360x over previous
#include <cuda_runtime.h>
#include <cuda_fp16.h>
#include <cstdint>

#define N_NODES 20000
#define N_EDGES 320000
#define ET      (N_EDGES + N_NODES)   // 340000
#define GCN_IN  256
#define C1      128
#define H1      5
#define F1      (H1*C1)               // 640
#define C2      128
#define H2      3
#define F2      (H2*C2)               // 384
#define N_BBOX  4096
#define NB_SCAN ((N_NODES + 1023) / 1024)   // 20
#define MAXDEG  256                   // degree cap for smem softmax (Poisson(16)+1)

// ---------------- scratch ---------------------------------------------------
__device__ int    g_is64;
__device__ int    g_cnt[N_NODES];
__device__ int    g_cur[N_NODES];
__device__ int    g_off[N_NODES + 1];
__device__ int    g_src[ET];
__device__ int    g_bsum[32];
__device__ int    g_bpre[32];
__device__ __half g_xh[(size_t)N_NODES * GCN_IN];   // x as fp16
__device__ __half g_w1h[F1 * GCN_IN];               // W1^T fp16 [F1][256]
__device__ __half g_w2h[F2 * F1];                   // W2^T fp16 [F2][640]
__device__ __half g_h1h[(size_t)N_NODES * F1];      // h1 fp16 (gather-only)
__device__ __half g_h2h[(size_t)N_NODES * F2];      // h2 fp16 (gather-only)
__device__ __half g_o1h[(size_t)N_NODES * F1];      // layer1 out fp16 (gemm2 A)
__device__ float  g_as1[N_NODES * H1];
__device__ float  g_ad1[N_NODES * H1];
__device__ float  g_as2[N_NODES * H2];
__device__ float  g_ad2[N_NODES * H2];

__device__ __forceinline__ float leaky(float x, float s) {
    return x >= 0.f ? x : s * x;
}
__device__ __forceinline__ int load_idx(const void* p, long long i) {
    return g_is64 ? (int)((const long long*)p)[i] : ((const int*)p)[i];
}
__device__ __forceinline__ void ldm_x4(uint32_t (&r)[4], uint32_t addr) {
    asm volatile("ldmatrix.sync.aligned.m8n8.x4.shared.b16 {%0,%1,%2,%3}, [%4];"
                 : "=r"(r[0]), "=r"(r[1]), "=r"(r[2]), "=r"(r[3]) : "r"(addr));
}

// ---------------- prep: dtype sniff + counter zero --------------------------
__global__ void k_prep(const void* ei) {
    int i = blockIdx.x * blockDim.x + threadIdx.x;
    if (i == 0) {
        const int* p = (const int*)ei;
        int nz = 0;
        #pragma unroll
        for (int j = 0; j < 64; j++) nz |= p[2 * j + 1];
        g_is64 = (nz == 0) ? 1 : 0;
    }
    if (i < N_NODES) { g_cnt[i] = 0; g_cur[i] = 0; }
}

// ---------------- fp32 -> fp16 convert (8 elems/thread) ---------------------
__global__ void k_tohalf(const float* __restrict__ in, __half* __restrict__ out, int n8) {
    int i = blockIdx.x * blockDim.x + threadIdx.x;
    if (i >= n8) return;
    float4 v0 = reinterpret_cast<const float4*>(in)[2 * i];
    float4 v1 = reinterpret_cast<const float4*>(in)[2 * i + 1];
    __half2 h[4];
    h[0] = __floats2half2_rn(v0.x, v0.y);
    h[1] = __floats2half2_rn(v0.z, v0.w);
    h[2] = __floats2half2_rn(v1.x, v1.y);
    h[3] = __floats2half2_rn(v1.z, v1.w);
    reinterpret_cast<uint4*>(out)[i] = *reinterpret_cast<uint4*>(h);
}

// ---------------- transpose -> fp16: W[K][N] -> Wt[N][K] --------------------
__global__ void k_transpose_h(const float* __restrict__ in, __half* __restrict__ out,
                              int K, int N) {
    __shared__ float tile[32][33];
    int n0 = blockIdx.x * 32, k0 = blockIdx.y * 32;
    int tx = threadIdx.x, ty = threadIdx.y;
    #pragma unroll
    for (int j = 0; j < 32; j += 8)
        tile[ty + j][tx] = in[(size_t)(k0 + ty + j) * N + n0 + tx];
    __syncthreads();
    #pragma unroll
    for (int j = 0; j < 32; j += 8)
        out[(size_t)(n0 + ty + j) * K + k0 + tx] = __float2half(tile[tx][ty + j]);
}

// ---------------- CSR build -------------------------------------------------
__global__ void k_hist(const void* __restrict__ ei) {
    int e = blockIdx.x * blockDim.x + threadIdx.x;
    if (e >= ET) return;
    int dst = (e < N_EDGES) ? load_idx(ei, (long long)N_EDGES + e) : (e - N_EDGES);
    atomicAdd(&g_cnt[dst], 1);
}

__global__ void k_scan1() {
    __shared__ int ws[32];
    int tid = threadIdx.x, lane = tid & 31, wid = tid >> 5;
    int i = blockIdx.x * 1024 + tid;
    int v = (i < N_NODES) ? g_cnt[i] : 0;
    int x = v;
    #pragma unroll
    for (int o = 1; o < 32; o <<= 1) {
        int y = __shfl_up_sync(~0u, x, o);
        if (lane >= o) x += y;
    }
    if (lane == 31) ws[wid] = x;
    __syncthreads();
    if (wid == 0) {
        int w = ws[lane];
        #pragma unroll
        for (int o = 1; o < 32; o <<= 1) {
            int y = __shfl_up_sync(~0u, w, o);
            if (lane >= o) w += y;
        }
        ws[lane] = w;
    }
    __syncthreads();
    int incl = x + (wid > 0 ? ws[wid - 1] : 0);
    if (i < N_NODES) g_off[i + 1] = incl;
    if (tid == 1023) g_bsum[blockIdx.x] = incl;
}

__global__ void k_scan2() {
    int lane = threadIdx.x;
    int v = (lane < NB_SCAN) ? g_bsum[lane] : 0;
    int x = v;
    #pragma unroll
    for (int o = 1; o < 32; o <<= 1) {
        int y = __shfl_up_sync(~0u, x, o);
        if (lane >= o) x += y;
    }
    g_bpre[lane] = x - v;
}

__global__ void k_scan3() {
    int i = blockIdx.x * 1024 + threadIdx.x;
    if (i == 0) g_off[0] = 0;
    if (i < N_NODES) g_off[i + 1] += g_bpre[blockIdx.x];
}

__global__ void k_scatter(const void* __restrict__ ei) {
    int e = blockIdx.x * blockDim.x + threadIdx.x;
    if (e >= ET) return;
    int src, dst;
    if (e < N_EDGES) {
        src = load_idx(ei, e);
        dst = load_idx(ei, (long long)N_EDGES + e);
    } else {
        src = dst = e - N_EDGES;
    }
    int p = g_off[dst] + atomicAdd(&g_cur[dst], 1);
    g_src[p] = src;
}

// ---------------- FP16 GEMM (m16n8k16) — high occupancy ---------------------
#define GBM 64
#define GBN 128
#define GBK 32
#define SAh 40
#define STG 3
#define A_STAGE_H (GBM * SAh)               // 2560 halves
#define B_STAGE_H (GBN * SAh)               // 5120 halves
#define GEMM_SMEM (STG * (A_STAGE_H + B_STAGE_H) * 2)   // 46080 B

template<int MODE>
__global__ void __launch_bounds__(256, 3)
gemm_f16(const float* __restrict__ asrc, const float* __restrict__ adst) {
    const int M = N_NODES;
    const int K = (MODE == 0) ? GCN_IN : F1;
    const int N = (MODE == 0) ? F1 : F2;
    const int H = (MODE == 0) ? H1 : H2;
    const __half* A  = (MODE == 0) ? (const __half*)g_xh  : (const __half*)g_o1h;
    const __half* Bt = (MODE == 0) ? (const __half*)g_w1h : (const __half*)g_w2h;
    __half* Ch = (MODE == 0) ? g_h1h : g_h2h;
    float* oas = (MODE == 0) ? g_as1 : g_as2;
    float* oad = (MODE == 0) ? g_ad1 : g_ad2;

    extern __shared__ __half smemh[];
    __half* As = smemh;
    __half* Bs = smemh + STG * A_STAGE_H;
    __shared__ float red_s[4][GBM], red_d[4][GBM];

    int tid = threadIdx.x, lane = tid & 31, warp = tid >> 5;
    int warp_m = (warp & 1) * 32;
    int warp_n = (warp >> 1) * 32;
    int ngrp = warp >> 1;
    int head = blockIdx.x;
    int rb = blockIdx.y * GBM, cb = head * GBN;
    int grp = lane >> 2, sub = lane & 3;

    uint32_t sAb = (uint32_t)__cvta_generic_to_shared(As);
    uint32_t sBb = (uint32_t)__cvta_generic_to_shared(Bs);
    int mi = lane >> 3, r = lane & 7;
    uint32_t aoff = sAb + (((warp_m + r + 8 * (mi & 1)) * SAh + 8 * (mi >> 1)) << 1);
    uint32_t boff = sBb + (((warp_n + r + 8 * (mi >> 1)) * SAh + 8 * (mi & 1)) << 1);

    float acc[2][4][4];
    #pragma unroll
    for (int i = 0; i < 2; i++)
        #pragma unroll
        for (int j = 0; j < 4; j++)
            #pragma unroll
            for (int q = 0; q < 4; q++) acc[i][j][q] = 0.f;

    auto copy_tile = [&](int t, int buf) {
        int k0 = t * GBK;
        __half* Ab = As + buf * A_STAGE_H;
        __half* Bb = Bs + buf * B_STAGE_H;
        #pragma unroll
        for (int p = 0; p < 3; p++) {
            int c = p * 256 + tid;
            if (c < 256) {
                int row = c >> 2, col = (c & 3) * 8;
                const __half* src = A + (size_t)(rb + row) * K + k0 + col;
                uint32_t dst = (uint32_t)__cvta_generic_to_shared(&Ab[row * SAh + col]);
                int sz = (rb + row < M) ? 16 : 0;
                asm volatile("cp.async.cg.shared.global [%0], [%1], 16, %2;\n"
                             :: "r"(dst), "l"(src), "r"(sz));
            } else {
                int cB = c - 256;
                int row = cB >> 2, col = (cB & 3) * 8;
                const __half* src = Bt + (size_t)(cb + row) * K + k0 + col;
                uint32_t dst = (uint32_t)__cvta_generic_to_shared(&Bb[row * SAh + col]);
                asm volatile("cp.async.cg.shared.global [%0], [%1], 16;\n"
                             :: "r"(dst), "l"(src));
            }
        }
        asm volatile("cp.async.commit_group;\n" ::: "memory");
    };

    const int T = K / GBK;
    copy_tile(0, 0);
    copy_tile(1, 1);

    for (int t = 0; t < T; t++) {
        if (t < T - 1)
            asm volatile("cp.async.wait_group 1;\n" ::: "memory");
        else
            asm volatile("cp.async.wait_group 0;\n" ::: "memory");
        __syncthreads();
        if (t + 2 < T) copy_tile(t + 2, (t + 2) % STG);

        int buf = t % STG;
        uint32_t aB = aoff + buf * (A_STAGE_H * 2);
        uint32_t bB = boff + buf * (B_STAGE_H * 2);

        #pragma unroll
        for (int ks = 0; ks < 2; ks++) {
            uint32_t a0[4], a1[4];
            ldm_x4(a0, aB + ks * 32);
            ldm_x4(a1, aB + ks * 32 + 16 * SAh * 2);
            #pragma unroll
            for (int nt2 = 0; nt2 < 2; nt2++) {
                uint32_t b[4];
                ldm_x4(b, bB + ks * 32 + nt2 * (16 * SAh * 2));
                #pragma unroll
                for (int mt = 0; mt < 2; mt++) {
                    const uint32_t* a = (mt == 0) ? a0 : a1;
                    asm volatile(
                        "mma.sync.aligned.m16n8k16.row.col.f32.f16.f16.f32 "
                        "{%0,%1,%2,%3}, {%4,%5,%6,%7}, {%8,%9}, {%0,%1,%2,%3};"
                        : "+f"(acc[mt][2 * nt2][0]), "+f"(acc[mt][2 * nt2][1]),
                          "+f"(acc[mt][2 * nt2][2]), "+f"(acc[mt][2 * nt2][3])
                        : "r"(a[0]), "r"(a[1]), "r"(a[2]), "r"(a[3]),
                          "r"(b[0]), "r"(b[1]));
                    asm volatile(
                        "mma.sync.aligned.m16n8k16.row.col.f32.f16.f16.f32 "
                        "{%0,%1,%2,%3}, {%4,%5,%6,%7}, {%8,%9}, {%0,%1,%2,%3};"
                        : "+f"(acc[mt][2 * nt2 + 1][0]), "+f"(acc[mt][2 * nt2 + 1][1]),
                          "+f"(acc[mt][2 * nt2 + 1][2]), "+f"(acc[mt][2 * nt2 + 1][3])
                        : "r"(a[0]), "r"(a[1]), "r"(a[2]), "r"(a[3]),
                          "r"(b[2]), "r"(b[3]));
                }
            }
        }
    }

    // ---- store C as fp16 ----
    #pragma unroll
    for (int mt = 0; mt < 2; mt++) {
        int r0 = rb + warp_m + mt * 16 + grp;
        #pragma unroll
        for (int nt = 0; nt < 4; nt++) {
            int c0 = cb + warp_n + nt * 8 + 2 * sub;
            if (r0 < M)
                *reinterpret_cast<__half2*>(Ch + (size_t)r0 * N + c0) =
                    __floats2half2_rn(acc[mt][nt][0], acc[mt][nt][1]);
            if (r0 + 8 < M)
                *reinterpret_cast<__half2*>(Ch + (size_t)(r0 + 8) * N + c0) =
                    __floats2half2_rn(acc[mt][nt][2], acc[mt][nt][3]);
        }
    }

    // ---- fused attention dots ----
    float ps[2][2] = {{0.f, 0.f}, {0.f, 0.f}};
    float pd[2][2] = {{0.f, 0.f}, {0.f, 0.f}};
    #pragma unroll
    for (int nt = 0; nt < 4; nt++) {
        int cc = warp_n + nt * 8 + 2 * sub;
        float s0 = asrc[head * 128 + cc],     d0 = adst[head * 128 + cc];
        float s1 = asrc[head * 128 + cc + 1], d1 = adst[head * 128 + cc + 1];
        #pragma unroll
        for (int mt = 0; mt < 2; mt++) {
            ps[mt][0] += acc[mt][nt][0] * s0 + acc[mt][nt][1] * s1;
            pd[mt][0] += acc[mt][nt][0] * d0 + acc[mt][nt][1] * d1;
            ps[mt][1] += acc[mt][nt][2] * s0 + acc[mt][nt][3] * s1;
            pd[mt][1] += acc[mt][nt][2] * d0 + acc[mt][nt][3] * d1;
        }
    }
    #pragma unroll
    for (int mt = 0; mt < 2; mt++)
        #pragma unroll
        for (int hf = 0; hf < 2; hf++) {
            #pragma unroll
            for (int o = 1; o < 4; o <<= 1) {
                ps[mt][hf] += __shfl_xor_sync(~0u, ps[mt][hf], o);
                pd[mt][hf] += __shfl_xor_sync(~0u, pd[mt][hf], o);
            }
        }
    if (sub == 0) {
        #pragma unroll
        for (int mt = 0; mt < 2; mt++)
            #pragma unroll
            for (int hf = 0; hf < 2; hf++) {
                int lr = warp_m + mt * 16 + hf * 8 + grp;
                red_s[ngrp][lr] = ps[mt][hf];
                red_d[ngrp][lr] = pd[mt][hf];
            }
    }
    __syncthreads();
    if (ngrp == 0 && sub == 0) {
        #pragma unroll
        for (int mt = 0; mt < 2; mt++)
            #pragma unroll
            for (int hf = 0; hf < 2; hf++) {
                int lr = warp_m + mt * 16 + hf * 8 + grp;
                int rr = rb + lr;
                if (rr < M) {
                    float ts = red_s[0][lr] + red_s[1][lr] + red_s[2][lr] + red_s[3][lr];
                    float td = red_d[0][lr] + red_d[1][lr] + red_d[2][lr] + red_d[3][lr];
                    oas[rr * H + head] = ts;
                    oad[rr * H + head] = td;
                }
            }
    }
}

// ---------------- fused softmax + layer-1 aggregation -----------------------
__global__ void k_agg1(const float* __restrict__ b1) {
    __shared__ float s_alpha[MAXDEG][H1];
    int n = blockIdx.x;
    int head = threadIdx.x >> 5;           // 0..4
    int lane = threadIdx.x & 31;
    int c = head * 128 + lane * 4;
    int beg = g_off[n], end = g_off[n + 1];
    int deg = end - beg;
    float adv = g_ad1[n * H1 + head];

    float m = -1e30f;
    for (int i = beg + lane; i < end; i += 32) {
        int s = g_src[i];
        float e = leaky(g_as1[s * H1 + head] + adv, 0.2f);
        int idx = i - beg;
        if (idx < MAXDEG) s_alpha[idx][head] = e;
        m = fmaxf(m, e);
    }
    #pragma unroll
    for (int o = 16; o; o >>= 1) m = fmaxf(m, __shfl_xor_sync(~0u, m, o));
    __syncwarp();

    float sum = 0.f;
    for (int idx = lane; idx < deg; idx += 32) {
        float ex;
        if (idx < MAXDEG) {
            ex = expf(s_alpha[idx][head] - m);
            s_alpha[idx][head] = ex;
        } else {
            int s = g_src[beg + idx];
            ex = expf(leaky(g_as1[s * H1 + head] + adv, 0.2f) - m);
        }
        sum += ex;
    }
    #pragma unroll
    for (int o = 16; o; o >>= 1) sum += __shfl_xor_sync(~0u, sum, o);
    float rinv = 1.f / (sum + 1e-16f);
    __syncwarp();

    float4 acc = make_float4(0.f, 0.f, 0.f, 0.f);
    int i = beg;
    for (; i + 4 <= end && (i - beg) + 4 <= MAXDEG; i += 4) {
        int idx = i - beg;
        int s0 = g_src[i], s1 = g_src[i + 1], s2 = g_src[i + 2], s3 = g_src[i + 3];
        float a0 = s_alpha[idx][head];
        float a1 = s_alpha[idx + 1][head];
        float a2 = s_alpha[idx + 2][head];
        float a3 = s_alpha[idx + 3][head];
        uint2 u0 = *reinterpret_cast<const uint2*>(g_h1h + (size_t)s0 * F1 + c);
        uint2 u1 = *reinterpret_cast<const uint2*>(g_h1h + (size_t)s1 * F1 + c);
        uint2 u2 = *reinterpret_cast<const uint2*>(g_h1h + (size_t)s2 * F1 + c);
        uint2 u3 = *reinterpret_cast<const uint2*>(g_h1h + (size_t)s3 * F1 + c);
        float2 p0a = __half22float2(*reinterpret_cast<__half2*>(&u0.x));
        float2 p0b = __half22float2(*reinterpret_cast<__half2*>(&u0.y));
        float2 p1a = __half22float2(*reinterpret_cast<__half2*>(&u1.x));
        float2 p1b = __half22float2(*reinterpret_cast<__half2*>(&u1.y));
        float2 p2a = __half22float2(*reinterpret_cast<__half2*>(&u2.x));
        float2 p2b = __half22float2(*reinterpret_cast<__half2*>(&u2.y));
        float2 p3a = __half22float2(*reinterpret_cast<__half2*>(&u3.x));
        float2 p3b = __half22float2(*reinterpret_cast<__half2*>(&u3.y));
        acc.x += a0 * p0a.x + a1 * p1a.x + a2 * p2a.x + a3 * p3a.x;
        acc.y += a0 * p0a.y + a1 * p1a.y + a2 * p2a.y + a3 * p3a.y;
        acc.z += a0 * p0b.x + a1 * p1b.x + a2 * p2b.x + a3 * p3b.x;
        acc.w += a0 * p0b.y + a1 * p1b.y + a2 * p2b.y + a3 * p3b.y;
    }
    for (; i < end; i++) {
        int idx = i - beg;
        int s = g_src[i];
        float a;
        if (idx < MAXDEG) a = s_alpha[idx][head];
        else a = expf(leaky(g_as1[s * H1 + head] + adv, 0.2f) - m);
        uint2 u = *reinterpret_cast<const uint2*>(g_h1h + (size_t)s * F1 + c);
        float2 pa = __half22float2(*reinterpret_cast<__half2*>(&u.x));
        float2 pb = __half22float2(*reinterpret_cast<__half2*>(&u.y));
        acc.x += a * pa.x; acc.y += a * pa.y; acc.z += a * pb.x; acc.w += a * pb.y;
    }
    float4 bb = *reinterpret_cast<const float4*>(b1 + c);
    __half2 h01 = __floats2half2_rn(leaky(acc.x * rinv + bb.x, 0.01f),
                                    leaky(acc.y * rinv + bb.y, 0.01f));
    __half2 h23 = __floats2half2_rn(leaky(acc.z * rinv + bb.z, 0.01f),
                                    leaky(acc.w * rinv + bb.w, 0.01f));
    uint2 st;
    st.x = *reinterpret_cast<uint32_t*>(&h01);
    st.y = *reinterpret_cast<uint32_t*>(&h23);
    *reinterpret_cast<uint2*>(g_o1h + (size_t)n * F1 + c) = st;
}

// ---------------- fused softmax + layer-2 aggregation (bbox only) -----------
__global__ void k_agg2(const void* __restrict__ bbox, const float* __restrict__ b2,
                       float* __restrict__ out) {
    __shared__ float s_alpha[MAXDEG][H2];
    __shared__ float4 red[H2][32];
    int bi = blockIdx.x;
    int head = threadIdx.x >> 5;           // 0..2
    int lane = threadIdx.x & 31;
    int c = head * 128 + lane * 4;
    int n = load_idx(bbox, bi);
    int beg = g_off[n], end = g_off[n + 1];
    int deg = end - beg;
    float adv = g_ad2[n * H2 + head];

    float m = -1e30f;
    for (int i = beg + lane; i < end; i += 32) {
        int s = g_src[i];
        float e = leaky(g_as2[s * H2 + head] + adv, 0.2f);
        int idx = i - beg;
        if (idx < MAXDEG) s_alpha[idx][head] = e;
        m = fmaxf(m, e);
    }
    #pragma unroll
    for (int o = 16; o; o >>= 1) m = fmaxf(m, __shfl_xor_sync(~0u, m, o));
    __syncwarp();

    float sum = 0.f;
    for (int idx = lane; idx < deg; idx += 32) {
        float ex;
        if (idx < MAXDEG) {
            ex = expf(s_alpha[idx][head] - m);
            s_alpha[idx][head] = ex;
        } else {
            int s = g_src[beg + idx];
            ex = expf(leaky(g_as2[s * H2 + head] + adv, 0.2f) - m);
        }
        sum += ex;
    }
    #pragma unroll
    for (int o = 16; o; o >>= 1) sum += __shfl_xor_sync(~0u, sum, o);
    float rinv = 1.f / (sum + 1e-16f);
    __syncwarp();

    float4 acc = make_float4(0.f, 0.f, 0.f, 0.f);
    int e = beg;
    for (; e + 4 <= end && (e - beg) + 4 <= MAXDEG; e += 4) {
        int idx = e - beg;
        int s0 = g_src[e], s1 = g_src[e + 1], s2 = g_src[e + 2], s3 = g_src[e + 3];
        float a0 = s_alpha[idx][head];
        float a1 = s_alpha[idx + 1][head];
        float a2 = s_alpha[idx + 2][head];
        float a3 = s_alpha[idx + 3][head];
        uint2 u0 = *reinterpret_cast<const uint2*>(g_h2h + (size_t)s0 * F2 + c);
        uint2 u1 = *reinterpret_cast<const uint2*>(g_h2h + (size_t)s1 * F2 + c);
        uint2 u2 = *reinterpret_cast<const uint2*>(g_h2h + (size_t)s2 * F2 + c);
        uint2 u3 = *reinterpret_cast<const uint2*>(g_h2h + (size_t)s3 * F2 + c);
        float2 p0a = __half22float2(*reinterpret_cast<__half2*>(&u0.x));
        float2 p0b = __half22float2(*reinterpret_cast<__half2*>(&u0.y));
        float2 p1a = __half22float2(*reinterpret_cast<__half2*>(&u1.x));
        float2 p1b = __half22float2(*reinterpret_cast<__half2*>(&u1.y));
        float2 p2a = __half22float2(*reinterpret_cast<__half2*>(&u2.x));
        float2 p2b = __half22float2(*reinterpret_cast<__half2*>(&u2.y));
        float2 p3a = __half22float2(*reinterpret_cast<__half2*>(&u3.x));
        float2 p3b = __half22float2(*reinterpret_cast<__half2*>(&u3.y));
        acc.x += a0 * p0a.x + a1 * p1a.x + a2 * p2a.x + a3 * p3a.x;
        acc.y += a0 * p0a.y + a1 * p1a.y + a2 * p2a.y + a3 * p3a.y;
        acc.z += a0 * p0b.x + a1 * p1b.x + a2 * p2b.x + a3 * p3b.x;
        acc.w += a0 * p0b.y + a1 * p1b.y + a2 * p2b.y + a3 * p3b.y;
    }
    for (; e < end; e++) {
        int idx = e - beg;
        int s = g_src[e];
        float a;
        if (idx < MAXDEG) a = s_alpha[idx][head];
        else a = expf(leaky(g_as2[s * H2 + head] + adv, 0.2f) - m);
        uint2 u = *reinterpret_cast<const uint2*>(g_h2h + (size_t)s * F2 + c);
        float2 pa = __half22float2(*reinterpret_cast<__half2*>(&u.x));
        float2 pb = __half22float2(*reinterpret_cast<__half2*>(&u.y));
        acc.x += a * pa.x; acc.y += a * pa.y; acc.z += a * pb.x; acc.w += a * pb.y;
    }
    acc.x *= rinv; acc.y *= rinv; acc.z *= rinv; acc.w *= rinv;
    red[head][lane] = acc;
    __syncthreads();
    if (head == 0) {
        float4 r0 = red[0][lane], r1 = red[1][lane], r2 = red[2][lane];
        float4 bb = *reinterpret_cast<const float4*>(b2 + lane * 4);
        float4 o;
        o.x = leaky((r0.x + r1.x + r2.x) * (1.f / 3.f) + bb.x, 0.01f);
        o.y = leaky((r0.y + r1.y + r2.y) * (1.f / 3.f) + bb.y, 0.01f);
        o.z = leaky((r0.z + r1.z + r2.z) * (1.f / 3.f) + bb.z, 0.01f);
        o.w = leaky((r0.w + r1.w + r2.w) * (1.f / 3.f) + bb.w, 0.01f);
        *reinterpret_cast<float4*>(out + (size_t)bi * 128 + lane * 4) = o;
    }
}

// ---------------- launch: fork CSR chain onto a second stream ----------------
extern "C" void kernel_launch(void* const* d_in, const int* in_sizes, int n_in,
                              void* d_out, int out_size) {
    const float *x = nullptr, *W1 = nullptr, *W2 = nullptr, *b1 = nullptr, *b2 = nullptr;
    const float *att_src1 = nullptr, *att_dst1 = nullptr;
    const float *att_src2 = nullptr, *att_dst2 = nullptr;
    const void *ei = nullptr, *bbox = nullptr;
    int n640 = 0, n384 = 0;
    for (int i = 0; i < n_in; i++) {
        switch (in_sizes[i]) {
            case N_NODES * GCN_IN: x    = (const float*)d_in[i]; break;
            case 2 * N_EDGES:      ei   = d_in[i]; break;
            case N_BBOX:           bbox = d_in[i]; break;
            case GCN_IN * F1:      W1   = (const float*)d_in[i]; break;
            case F1 * F2:      W2   = (const float*)d_in[i]; break;
            case C2:               b2   = (const float*)d_in[i]; break;
            case F1:
                if      (n640 == 0) att_src1 = (const float*)d_in[i];
                else if (n640 == 1) att_dst1 = (const float*)d_in[i];
                else                b1       = (const float*)d_in[i];
                n640++; break;
            case F2:
                if (n384 == 0) att_src2 = (const float*)d_in[i];
                else           att_dst2 = (const float*)d_in[i];
                n384++; break;
            default: break;
        }
    }
    float* out = (float*)d_out;

    __half *xh, *w1h, *w2h;
    cudaGetSymbolAddress((void**)&xh,  g_xh);
    cudaGetSymbolAddress((void**)&w1h, g_w1h);
    cudaGetSymbolAddress((void**)&w2h, g_w2h);

    // persistent side stream + events (created on first, uncaptured, call)
    static cudaStream_t s2 = nullptr;
    static cudaEvent_t evFork = nullptr, evJoin = nullptr;
    if (s2 == nullptr) {
        cudaStreamCreateWithFlags(&s2, cudaStreamNonBlocking);
        cudaEventCreateWithFlags(&evFork, cudaEventDisableTiming);
        cudaEventCreateWithFlags(&evJoin, cudaEventDisableTiming);
        cudaFuncSetAttribute(gemm_f16<0>, cudaFuncAttributeMaxDynamicSharedMemorySize, GEMM_SMEM);
        cudaFuncSetAttribute(gemm_f16<1>, cudaFuncAttributeMaxDynamicSharedMemorySize, GEMM_SMEM);
    }

    // fork: CSR chain on s2, dense chain on default stream
    cudaEventRecord(evFork, 0);
    cudaStreamWaitEvent(s2, evFork, 0);

    k_prep<<<(N_NODES + 255) / 256, 256, 0, s2>>>(ei);
    k_hist<<<(ET + 255) / 256, 256, 0, s2>>>(ei);
    k_scan1<<<NB_SCAN, 1024, 0, s2>>>();
    k_scan2<<<1, 32, 0, s2>>>();
    k_scan3<<<NB_SCAN, 1024, 0, s2>>>();
    k_scatter<<<(ET + 255) / 256, 256, 0, s2>>>(ei);
    cudaEventRecord(evJoin, s2);

    k_tohalf<<<(N_NODES * GCN_IN / 8 + 255) / 256, 256>>>(x, xh, N_NODES * GCN_IN / 8);
    k_transpose_h<<<dim3(F1 / 32, GCN_IN / 32), dim3(32, 8)>>>(W1, w1h, GCN_IN, F1);
    {
        dim3 g(F1 / GBN, (N_NODES + GBM - 1) / GBM);
        gemm_f16<0><<<g, 256, GEMM_SMEM>>>(att_src1, att_dst1);
    }
    k_transpose_h<<<dim3(F2 / 32, F1 / 32), dim3(32, 8)>>>(W2, w2h, F1, F2);

    // join: agg1 needs CSR + gemm1
    cudaStreamWaitEvent(0, evJoin, 0);
    k_agg1<<<N_NODES, H1 * 32>>>(b1);

    {
        dim3 g(F2 / GBN, (N_NODES + GBM - 1) / GBM);
        gemm_f16<1><<<g, 256, GEMM_SMEM>>>(att_src2, att_dst2);
    }
    k_agg2<<<N_BBOX, H2 * 32>>>(bbox, b2, out);
}